// round 1
// baseline (speedup 1.0000x reference)
#include <cuda_runtime.h>
#include <math.h>

// Problem constants
#define BATCH 4
#define SEQL  2048
#define DIM   1024
#define NHEAD 16
#define HD    64
#define D3    (3*DIM)

// ---------------------------------------------------------------------------
// Scratch (static device globals — no allocation allowed)
// ---------------------------------------------------------------------------
__device__ float g_qkv[(size_t)BATCH*SEQL*D3];          // [B*S, 3*D]
__device__ float g_q[(size_t)BATCH*NHEAD*SEQL*HD];      // [B,H,S,HD]
__device__ float g_k[(size_t)BATCH*NHEAD*SEQL*HD];
__device__ float g_v[(size_t)BATCH*NHEAD*SEQL*HD];
__device__ float g_attn[(size_t)BATCH*SEQL*DIM];        // [B*S, D]

// ---------------------------------------------------------------------------
// SGEMM: C[M,N] = A[M,K] @ B[K,N] + bias[N]
// BM=BN=128, BK=8, 256 threads, 8x8 microtile. M%128==0, N%128==0, K%8==0.
// ---------------------------------------------------------------------------
#define LDA_S 132   // padded stride for As to kill store bank conflicts

__global__ __launch_bounds__(256) void sgemm_bias(
    const float* __restrict__ A, const float* __restrict__ B,
    const float* __restrict__ bias, float* __restrict__ C,
    int M, int N, int K)
{
    __shared__ float As[8 * LDA_S];   // transposed: As[k][m]
    __shared__ float Bs[8 * 128];     // Bs[k][n]

    const int tid  = threadIdx.x;
    const int crow = blockIdx.y;      // M tile
    const int ccol = blockIdx.x;      // N tile

    const float* Ab = A + (size_t)crow * 128 * K;
    const float* Bb = B + (size_t)ccol * 128;
    float*       Cb = C + (size_t)crow * 128 * N + (size_t)ccol * 128;

    const int aRow = tid >> 1;            // 0..127
    const int aCol = (tid & 1) * 4;       // 0 or 4
    const int bRow = tid >> 5;            // 0..7
    const int bCol = (tid & 31) * 4;      // 0..124
    const int tRow = tid >> 4;            // 0..15
    const int tCol = tid & 15;            // 0..15

    float acc[8][8];
    #pragma unroll
    for (int i = 0; i < 8; i++)
        #pragma unroll
        for (int j = 0; j < 8; j++) acc[i][j] = 0.f;

    for (int bk = 0; bk < K; bk += 8) {
        float4 a = *(const float4*)(Ab + (size_t)aRow * K + bk + aCol);
        As[(aCol + 0) * LDA_S + aRow] = a.x;
        As[(aCol + 1) * LDA_S + aRow] = a.y;
        As[(aCol + 2) * LDA_S + aRow] = a.z;
        As[(aCol + 3) * LDA_S + aRow] = a.w;
        float4 b4 = *(const float4*)(Bb + (size_t)(bk + bRow) * N + bCol);
        *(float4*)(Bs + bRow * 128 + bCol) = b4;
        __syncthreads();

        #pragma unroll
        for (int d = 0; d < 8; d++) {
            float rm[8], rn[8];
            *(float4*)(rm)     = *(const float4*)(As + d * LDA_S + tRow * 8);
            *(float4*)(rm + 4) = *(const float4*)(As + d * LDA_S + tRow * 8 + 4);
            *(float4*)(rn)     = *(const float4*)(Bs + d * 128 + tCol * 8);
            *(float4*)(rn + 4) = *(const float4*)(Bs + d * 128 + tCol * 8 + 4);
            #pragma unroll
            for (int i = 0; i < 8; i++)
                #pragma unroll
                for (int j = 0; j < 8; j++)
                    acc[i][j] += rm[i] * rn[j];
        }
        __syncthreads();
    }

    #pragma unroll
    for (int i = 0; i < 8; i++) {
        const int r = tRow * 8 + i;
        #pragma unroll
        for (int j = 0; j < 8; j += 4) {
            const int c = tCol * 8 + j;
            float4 o;
            o.x = acc[i][j + 0] + bias[ccol * 128 + c + 0];
            o.y = acc[i][j + 1] + bias[ccol * 128 + c + 1];
            o.z = acc[i][j + 2] + bias[ccol * 128 + c + 2];
            o.w = acc[i][j + 3] + bias[ccol * 128 + c + 3];
            *(float4*)(Cb + (size_t)r * N + c) = o;
        }
    }
}

// ---------------------------------------------------------------------------
// RoPE + split: qkv[B*S, 3*D] -> q,k (rope-applied), v in [B,H,S,HD] layout.
// One thread per (b,h,s, d<32) pair. Angles in double (robust vs fast-math).
// ---------------------------------------------------------------------------
__global__ void rope_split_kernel(const float* __restrict__ qkv,
                                  float* __restrict__ q,
                                  float* __restrict__ k,
                                  float* __restrict__ v)
{
    const int idx = blockIdx.x * blockDim.x + threadIdx.x;
    // idx = (((b*NHEAD + h)*SEQL + s)*32 + d)
    const int d = idx & 31;
    const int s = (idx >> 5) & (SEQL - 1);
    const int h = (idx >> 16) & (NHEAD - 1);
    const int b = idx >> 20;

    const size_t base = ((size_t)(b * SEQL + s)) * D3 + h * HD;
    const float q1 = qkv[base + d],            q2 = qkv[base + d + 32];
    const float k1 = qkv[base + DIM + d],      k2 = qkv[base + DIM + d + 32];
    const float v1 = qkv[base + 2 * DIM + d],  v2 = qkv[base + 2 * DIM + d + 32];

    const double inv_freq = exp(-log(10000.0) * (double)(2 * d) / (double)HD);
    const double ang = (double)s * inv_freq;
    const float c  = (float)cos(ang);
    const float sn = (float)sin(ang);

    const size_t ob = ((size_t)((b * NHEAD + h) * SEQL + s)) * HD + d;
    q[ob]      = q1 * c - q2 * sn;
    q[ob + 32] = q1 * sn + q2 * c;
    k[ob]      = k1 * c - k2 * sn;
    k[ob + 32] = k1 * sn + k2 * c;
    v[ob]      = v1;
    v[ob + 32] = v2;
}

// ---------------------------------------------------------------------------
// Flash attention: per CTA = one (b,h) pair x one 64-row q tile.
// 256 threads, 16x16 thread grid, 4x4 microtiles. Online softmax via
// half-warp shuffles. Writes O in [B,S,D] layout (ready for out-proj GEMM).
// ---------------------------------------------------------------------------
#define FLASH_SMEM_FLOATS (3 * 64 * 65 + 64 * 64)
#define FLASH_SMEM_BYTES  (FLASH_SMEM_FLOATS * 4)

__global__ __launch_bounds__(256) void flash_kernel(
    const float* __restrict__ Q, const float* __restrict__ K,
    const float* __restrict__ V, float* __restrict__ O)
{
    extern __shared__ float sm[];
    float* Qs = sm;                 // 64 x 65
    float* Ks = sm + 64 * 65;       // 64 x 65
    float* Ss = sm + 2 * 64 * 65;   // 64 x 65 (P tile)
    float* Vs = sm + 3 * 64 * 65;   // 64 x 64 (float4-aligned)

    const int tid = threadIdx.x;
    const int bh  = blockIdx.y;          // 0..63
    const int qt  = blockIdx.x;          // 0..31
    const int b   = bh >> 4;
    const int h   = bh & 15;

    const float* Qg = Q + ((size_t)bh * SEQL + (size_t)qt * 64) * HD;
    const float* Kg = K + (size_t)bh * SEQL * HD;
    const float* Vg = V + (size_t)bh * SEQL * HD;

    // Load Q tile (64x64) once.
    for (int i = tid; i < 64 * 16; i += 256) {
        const int r = i >> 4;
        const int c = (i & 15) << 2;
        float4 t = *(const float4*)(Qg + r * HD + c);
        Qs[r * 65 + c + 0] = t.x;
        Qs[r * 65 + c + 1] = t.y;
        Qs[r * 65 + c + 2] = t.z;
        Qs[r * 65 + c + 3] = t.w;
    }

    const int tr = tid >> 4;   // 0..15 -> rows 4*tr..4*tr+3
    const int tc = tid & 15;   // 0..15 -> cols 4*tc..4*tc+3

    float acc[4][4];
    float m_run[4], l_run[4];
    #pragma unroll
    for (int i = 0; i < 4; i++) {
        m_run[i] = -1e30f;
        l_run[i] = 0.f;
        #pragma unroll
        for (int j = 0; j < 4; j++) acc[i][j] = 0.f;
    }

    const float scale = 0.125f;   // HD^-0.5

    for (int kt = 0; kt < SEQL / 64; kt++) {
        __syncthreads();   // guard smem reuse from previous iteration's PV

        // Load K,V tiles (64x64 each).
        for (int i = tid; i < 64 * 16; i += 256) {
            const int r = i >> 4;
            const int c = (i & 15) << 2;
            float4 t = *(const float4*)(Kg + (size_t)(kt * 64 + r) * HD + c);
            Ks[r * 65 + c + 0] = t.x;
            Ks[r * 65 + c + 1] = t.y;
            Ks[r * 65 + c + 2] = t.z;
            Ks[r * 65 + c + 3] = t.w;
            float4 u = *(const float4*)(Vg + (size_t)(kt * 64 + r) * HD + c);
            *(float4*)(Vs + r * 64 + c) = u;
        }
        __syncthreads();

        // S = Q @ K^T (64x64), each thread 4x4.
        float s_acc[4][4];
        #pragma unroll
        for (int i = 0; i < 4; i++)
            #pragma unroll
            for (int j = 0; j < 4; j++) s_acc[i][j] = 0.f;

        #pragma unroll 8
        for (int d = 0; d < 64; d++) {
            float qa[4], kb[4];
            #pragma unroll
            for (int i = 0; i < 4; i++) qa[i] = Qs[(tr * 4 + i) * 65 + d];
            #pragma unroll
            for (int j = 0; j < 4; j++) kb[j] = Ks[(tc * 4 + j) * 65 + d];
            #pragma unroll
            for (int i = 0; i < 4; i++)
                #pragma unroll
                for (int j = 0; j < 4; j++)
                    s_acc[i][j] += qa[i] * kb[j];
        }

        // Online softmax per row; row r is spread over 16 lanes of one
        // half-warp (lanes with same tr), so shfl_xor offsets 1,2,4,8 reduce it.
        #pragma unroll
        for (int i = 0; i < 4; i++) {
            float mx = -1e30f;
            #pragma unroll
            for (int j = 0; j < 4; j++) {
                s_acc[i][j] *= scale;
                mx = fmaxf(mx, s_acc[i][j]);
            }
            #pragma unroll
            for (int off = 1; off < 16; off <<= 1)
                mx = fmaxf(mx, __shfl_xor_sync(0xffffffffu, mx, off));
            const float m_new = fmaxf(m_run[i], mx);
            const float f = __expf(m_run[i] - m_new);
            float lsum = 0.f;
            #pragma unroll
            for (int j = 0; j < 4; j++) {
                const float p = __expf(s_acc[i][j] - m_new);
                s_acc[i][j] = p;
                lsum += p;
            }
            #pragma unroll
            for (int off = 1; off < 16; off <<= 1)
                lsum += __shfl_xor_sync(0xffffffffu, lsum, off);
            l_run[i] = l_run[i] * f + lsum;
            m_run[i] = m_new;
            #pragma unroll
            for (int j = 0; j < 4; j++) acc[i][j] *= f;
            #pragma unroll
            for (int j = 0; j < 4; j++)
                Ss[(tr * 4 + i) * 65 + tc * 4 + j] = s_acc[i][j];
        }
        __syncthreads();

        // acc += P @ V
        #pragma unroll 4
        for (int kk = 0; kk < 64; kk++) {
            float pv[4];
            #pragma unroll
            for (int i = 0; i < 4; i++) pv[i] = Ss[(tr * 4 + i) * 65 + kk];
            float4 vv = *(const float4*)(Vs + kk * 64 + tc * 4);
            #pragma unroll
            for (int i = 0; i < 4; i++) {
                acc[i][0] += pv[i] * vv.x;
                acc[i][1] += pv[i] * vv.y;
                acc[i][2] += pv[i] * vv.z;
                acc[i][3] += pv[i] * vv.w;
            }
        }
    }

    // Epilogue: normalize, write O[b, sq, h*64 + d] (i.e. [B*S, D] row-major).
    #pragma unroll
    for (int i = 0; i < 4; i++) {
        const float inv_l = 1.f / l_run[i];
        const int sq = qt * 64 + tr * 4 + i;
        float4 o;
        o.x = acc[i][0] * inv_l;
        o.y = acc[i][1] * inv_l;
        o.z = acc[i][2] * inv_l;
        o.w = acc[i][3] * inv_l;
        *(float4*)(O + ((size_t)(b * SEQL + sq)) * DIM + h * HD + tc * 4) = o;
    }
}

// ---------------------------------------------------------------------------
// Launch
// ---------------------------------------------------------------------------
extern "C" void kernel_launch(void* const* d_in, const int* in_sizes, int n_in,
                              void* d_out, int out_size)
{
    const float* x    = (const float*)d_in[0];   // [B,S,D]
    const float* Wqkv = (const float*)d_in[1];   // [D, 3D]
    const float* bqkv = (const float*)d_in[2];   // [3D]
    const float* Wout = (const float*)d_in[3];   // [D, D]
    const float* bout = (const float*)d_in[4];   // [D]
    float* out = (float*)d_out;                  // [B,S,D]

    void* p;
    cudaGetSymbolAddress(&p, g_qkv);  float* qkv  = (float*)p;
    cudaGetSymbolAddress(&p, g_q);    float* q    = (float*)p;
    cudaGetSymbolAddress(&p, g_k);    float* k    = (float*)p;
    cudaGetSymbolAddress(&p, g_v);    float* v    = (float*)p;
    cudaGetSymbolAddress(&p, g_attn); float* attn = (float*)p;

    cudaFuncSetAttribute(flash_kernel,
                         cudaFuncAttributeMaxDynamicSharedMemorySize,
                         FLASH_SMEM_BYTES);

    const int M = BATCH * SEQL;   // 8192

    // 1) QKV = x @ Wqkv + bqkv
    sgemm_bias<<<dim3(D3 / 128, M / 128), 256>>>(x, Wqkv, bqkv, qkv, M, D3, DIM);

    // 2) RoPE + split into q,k,v [B,H,S,HD]
    {
        const int total = BATCH * NHEAD * SEQL * 32;
        rope_split_kernel<<<total / 256, 256>>>(qkv, q, k, v);
    }

    // 3) Flash attention -> attn [B*S, D]
    flash_kernel<<<dim3(SEQL / 64, BATCH * NHEAD), 256, FLASH_SMEM_BYTES>>>(
        q, k, v, attn);

    // 4) out = attn @ Wout + bout
    sgemm_bias<<<dim3(DIM / 128, M / 128), 256>>>(attn, Wout, bout, out, M, DIM, DIM);
}

// round 3
// speedup vs baseline: 1.0066x; 1.0066x over previous
#include <cuda_runtime.h>
#include <math.h>

// Problem constants
#define BATCH 4
#define SEQL  2048
#define DIM   1024
#define NHEAD 16
#define HD    64
#define D3    (3*DIM)

// ---------------------------------------------------------------------------
// Scratch (static device globals — no allocation allowed)
// ---------------------------------------------------------------------------
__device__ float g_qkv[(size_t)BATCH*SEQL*D3];          // [B*S, 3*D]
__device__ float g_q[(size_t)BATCH*NHEAD*SEQL*HD];      // [B,H,S,HD]
__device__ float g_k[(size_t)BATCH*NHEAD*SEQL*HD];
__device__ float g_v[(size_t)BATCH*NHEAD*SEQL*HD];
__device__ float g_attn[(size_t)BATCH*SEQL*DIM];        // [B*S, D]

// ---------------------------------------------------------------------------
// SGEMM v2: C[M,N] = A[M,K] @ B[K,N] + bias[N]
// BM=BN=128, BK=16, 256 threads, 8x8 microtile, double-buffered smem +
// register prefetch. M%128==0, N%128==0, K%16==0.
// ---------------------------------------------------------------------------
#define LDA_S 132   // padded stride for As (transposed) to avoid conflicts
#define BKG   16

__global__ __launch_bounds__(256, 2) void sgemm_bias(
    const float* __restrict__ A, const float* __restrict__ B,
    const float* __restrict__ bias, float* __restrict__ C,
    int M, int N, int K)
{
    __shared__ float As[2][BKG][LDA_S];   // transposed: As[buf][k][m]
    __shared__ float Bs[2][BKG][128];     // Bs[buf][k][n]

    const int tid  = threadIdx.x;
    const int crow = blockIdx.y;      // M tile
    const int ccol = blockIdx.x;      // N tile

    const float* Ab = A + (size_t)crow * 128 * K;
    const float* Bb = B + (size_t)ccol * 128;
    float*       Cb = C + (size_t)crow * 128 * N + (size_t)ccol * 128;

    const int aRow  = tid >> 1;            // 0..127
    const int aCol0 = (tid & 1) * 8;       // 0 or 8 (two float4s: +0, +4)
    const int bRow  = tid >> 5;            // 0..7 (and +8)
    const int bCol  = (tid & 31) * 4;      // 0..124
    const int tRow  = tid >> 4;            // 0..15
    const int tCol  = tid & 15;            // 0..15

    float acc[8][8];
    #pragma unroll
    for (int i = 0; i < 8; i++)
        #pragma unroll
        for (int j = 0; j < 8; j++) acc[i][j] = 0.f;

    // ---- load tile 0 into buffer 0 ----
    {
        float4 a0 = *(const float4*)(Ab + (size_t)aRow * K + aCol0);
        float4 a1 = *(const float4*)(Ab + (size_t)aRow * K + aCol0 + 4);
        As[0][aCol0 + 0][aRow] = a0.x;
        As[0][aCol0 + 1][aRow] = a0.y;
        As[0][aCol0 + 2][aRow] = a0.z;
        As[0][aCol0 + 3][aRow] = a0.w;
        As[0][aCol0 + 4][aRow] = a1.x;
        As[0][aCol0 + 5][aRow] = a1.y;
        As[0][aCol0 + 6][aRow] = a1.z;
        As[0][aCol0 + 7][aRow] = a1.w;
        float4 b0 = *(const float4*)(Bb + (size_t)bRow * N + bCol);
        float4 b1 = *(const float4*)(Bb + (size_t)(bRow + 8) * N + bCol);
        *(float4*)(&Bs[0][bRow][bCol])     = b0;
        *(float4*)(&Bs[0][bRow + 8][bCol]) = b1;
    }
    __syncthreads();

    int buf = 0;
    for (int bk = 0; bk < K; bk += BKG) {
        const bool has_next = (bk + BKG) < K;
        float4 pa0, pa1, pb0, pb1;
        if (has_next) {
            const float* An = Ab + (size_t)aRow * K + bk + BKG;
            pa0 = *(const float4*)(An + aCol0);
            pa1 = *(const float4*)(An + aCol0 + 4);
            const float* Bn = Bb + (size_t)(bk + BKG) * N;
            pb0 = *(const float4*)(Bn + (size_t)bRow * N + bCol);
            pb1 = *(const float4*)(Bn + (size_t)(bRow + 8) * N + bCol);
        }

        // ---- compute on current buffer ----
        #pragma unroll
        for (int d = 0; d < BKG; d++) {
            float rm[8], rn[8];
            *(float4*)(rm)     = *(const float4*)(&As[buf][d][tRow * 8]);
            *(float4*)(rm + 4) = *(const float4*)(&As[buf][d][tRow * 8 + 4]);
            *(float4*)(rn)     = *(const float4*)(&Bs[buf][d][tCol * 8]);
            *(float4*)(rn + 4) = *(const float4*)(&Bs[buf][d][tCol * 8 + 4]);
            #pragma unroll
            for (int i = 0; i < 8; i++)
                #pragma unroll
                for (int j = 0; j < 8; j++)
                    acc[i][j] += rm[i] * rn[j];
        }

        if (has_next) {
            const int nb = buf ^ 1;
            As[nb][aCol0 + 0][aRow] = pa0.x;
            As[nb][aCol0 + 1][aRow] = pa0.y;
            As[nb][aCol0 + 2][aRow] = pa0.z;
            As[nb][aCol0 + 3][aRow] = pa0.w;
            As[nb][aCol0 + 4][aRow] = pa1.x;
            As[nb][aCol0 + 5][aRow] = pa1.y;
            As[nb][aCol0 + 6][aRow] = pa1.z;
            As[nb][aCol0 + 7][aRow] = pa1.w;
            *(float4*)(&Bs[nb][bRow][bCol])     = pb0;
            *(float4*)(&Bs[nb][bRow + 8][bCol]) = pb1;
            __syncthreads();
            buf = nb;
        }
    }

    #pragma unroll
    for (int i = 0; i < 8; i++) {
        const int r = tRow * 8 + i;
        #pragma unroll
        for (int j = 0; j < 8; j += 4) {
            const int c = tCol * 8 + j;
            float4 o;
            o.x = acc[i][j + 0] + bias[ccol * 128 + c + 0];
            o.y = acc[i][j + 1] + bias[ccol * 128 + c + 1];
            o.z = acc[i][j + 2] + bias[ccol * 128 + c + 2];
            o.w = acc[i][j + 3] + bias[ccol * 128 + c + 3];
            *(float4*)(Cb + (size_t)r * N + c) = o;
        }
    }
}

// ---------------------------------------------------------------------------
// RoPE + split: qkv[B*S, 3*D] -> q,k (rope-applied), v in [B,H,S,HD] layout.
// ---------------------------------------------------------------------------
__global__ void rope_split_kernel(const float* __restrict__ qkv,
                                  float* __restrict__ q,
                                  float* __restrict__ k,
                                  float* __restrict__ v)
{
    const int idx = blockIdx.x * blockDim.x + threadIdx.x;
    const int d = idx & 31;
    const int s = (idx >> 5) & (SEQL - 1);
    const int h = (idx >> 16) & (NHEAD - 1);
    const int b = idx >> 20;

    const size_t base = ((size_t)(b * SEQL + s)) * D3 + h * HD;
    const float q1 = qkv[base + d],            q2 = qkv[base + d + 32];
    const float k1 = qkv[base + DIM + d],      k2 = qkv[base + DIM + d + 32];
    const float v1 = qkv[base + 2 * DIM + d],  v2 = qkv[base + 2 * DIM + d + 32];

    const double inv_freq = exp(-log(10000.0) * (double)(2 * d) / (double)HD);
    const double ang = (double)s * inv_freq;
    const float c  = (float)cos(ang);
    const float sn = (float)sin(ang);

    const size_t ob = ((size_t)((b * NHEAD + h) * SEQL + s)) * HD + d;
    q[ob]      = q1 * c - q2 * sn;
    q[ob + 32] = q1 * sn + q2 * c;
    k[ob]      = k1 * c - k2 * sn;
    k[ob + 32] = k1 * sn + k2 * c;
    v[ob]      = v1;
    v[ob + 32] = v2;
}

// ---------------------------------------------------------------------------
// Flash attention v2: all smem traffic vectorized to LDS.128.
//   Qs [64][68]  row-major (q-row, d)       — broadcast float4 reads
//   Kst[64][68]  TRANSPOSED (d, k-col)      — coalesced float4 reads
//   Ss [64][68]  P tile (q-row, k-col)      — float4 writes + broadcast reads
//   Vs [64][64]  row-major (k-row, d)       — coalesced float4 reads
// ---------------------------------------------------------------------------
#define QS_LD 68
#define FLASH_SMEM_FLOATS (3 * 64 * QS_LD + 64 * 64)
#define FLASH_SMEM_BYTES  (FLASH_SMEM_FLOATS * 4)

__global__ __launch_bounds__(256) void flash_kernel(
    const float* __restrict__ Q, const float* __restrict__ K,
    const float* __restrict__ V, float* __restrict__ O)
{
    extern __shared__ float sm[];
    float* Qs  = sm;                    // 64 x 68
    float* Kst = sm + 64 * QS_LD;       // 64 x 68 (transposed K)
    float* Ss  = sm + 2 * 64 * QS_LD;   // 64 x 68
    float* Vs  = sm + 3 * 64 * QS_LD;   // 64 x 64

    const int tid = threadIdx.x;
    const int bh  = blockIdx.y;          // 0..63
    const int qt  = blockIdx.x;          // 0..31
    const int b   = bh >> 4;
    const int h   = bh & 15;

    const float* Qg = Q + ((size_t)bh * SEQL + (size_t)qt * 64) * HD;
    const float* Kg = K + (size_t)bh * SEQL * HD;
    const float* Vg = V + (size_t)bh * SEQL * HD;

    // Load Q tile (64x64) once.
    for (int i = tid; i < 64 * 16; i += 256) {
        const int r = i >> 4;
        const int c = (i & 15) << 2;
        float4 t = *(const float4*)(Qg + r * HD + c);
        *(float4*)(Qs + r * QS_LD + c) = t;
    }

    const int tr = tid >> 4;   // 0..15 -> rows 4*tr..4*tr+3
    const int tc = tid & 15;   // 0..15 -> cols 4*tc..4*tc+3

    float acc[4][4];
    float m_run[4], l_run[4];
    #pragma unroll
    for (int i = 0; i < 4; i++) {
        m_run[i] = -1e30f;
        l_run[i] = 0.f;
        #pragma unroll
        for (int j = 0; j < 4; j++) acc[i][j] = 0.f;
    }

    const float scale = 0.125f;   // HD^-0.5

    for (int kt = 0; kt < SEQL / 64; kt++) {
        __syncthreads();   // guard smem reuse from previous iteration

        // Load K (transposed into Kst) and V tiles.
        for (int i = tid; i < 64 * 16; i += 256) {
            const int r = i >> 4;          // token within tile
            const int c = (i & 15) << 2;   // dim
            float4 t = *(const float4*)(Kg + (size_t)(kt * 64 + r) * HD + c);
            Kst[(c + 0) * QS_LD + r] = t.x;
            Kst[(c + 1) * QS_LD + r] = t.y;
            Kst[(c + 2) * QS_LD + r] = t.z;
            Kst[(c + 3) * QS_LD + r] = t.w;
            float4 u = *(const float4*)(Vg + (size_t)(kt * 64 + r) * HD + c);
            *(float4*)(Vs + r * 64 + c) = u;
        }
        __syncthreads();

        // S = Q @ K^T : 4x4 per thread, all LDS.128.
        float s_acc[4][4];
        #pragma unroll
        for (int i = 0; i < 4; i++)
            #pragma unroll
            for (int j = 0; j < 4; j++) s_acc[i][j] = 0.f;

        #pragma unroll
        for (int d = 0; d < 64; d += 4) {
            float4 qa[4], kb[4];
            #pragma unroll
            for (int i = 0; i < 4; i++)
                qa[i] = *(const float4*)(Qs + (tr * 4 + i) * QS_LD + d);
            #pragma unroll
            for (int dd = 0; dd < 4; dd++)
                kb[dd] = *(const float4*)(Kst + (d + dd) * QS_LD + tc * 4);
            #pragma unroll
            for (int i = 0; i < 4; i++) {
                s_acc[i][0] += qa[i].x * kb[0].x + qa[i].y * kb[1].x
                             + qa[i].z * kb[2].x + qa[i].w * kb[3].x;
                s_acc[i][1] += qa[i].x * kb[0].y + qa[i].y * kb[1].y
                             + qa[i].z * kb[2].y + qa[i].w * kb[3].y;
                s_acc[i][2] += qa[i].x * kb[0].z + qa[i].y * kb[1].z
                             + qa[i].z * kb[2].z + qa[i].w * kb[3].z;
                s_acc[i][3] += qa[i].x * kb[0].w + qa[i].y * kb[1].w
                             + qa[i].z * kb[2].w + qa[i].w * kb[3].w;
            }
        }

        // Online softmax per row (row spread over 16 lanes -> shfl reduce).
        #pragma unroll
        for (int i = 0; i < 4; i++) {
            float mx = -1e30f;
            #pragma unroll
            for (int j = 0; j < 4; j++) {
                s_acc[i][j] *= scale;
                mx = fmaxf(mx, s_acc[i][j]);
            }
            #pragma unroll
            for (int off = 1; off < 16; off <<= 1)
                mx = fmaxf(mx, __shfl_xor_sync(0xffffffffu, mx, off));
            const float m_new = fmaxf(m_run[i], mx);
            const float f = __expf(m_run[i] - m_new);
            float lsum = 0.f;
            #pragma unroll
            for (int j = 0; j < 4; j++) {
                const float p = __expf(s_acc[i][j] - m_new);
                s_acc[i][j] = p;
                lsum += p;
            }
            #pragma unroll
            for (int off = 1; off < 16; off <<= 1)
                lsum += __shfl_xor_sync(0xffffffffu, lsum, off);
            l_run[i] = l_run[i] * f + lsum;
            m_run[i] = m_new;
            #pragma unroll
            for (int j = 0; j < 4; j++) acc[i][j] *= f;
            float4 pw;
            pw.x = s_acc[i][0]; pw.y = s_acc[i][1];
            pw.z = s_acc[i][2]; pw.w = s_acc[i][3];
            *(float4*)(Ss + (tr * 4 + i) * QS_LD + tc * 4) = pw;
        }
        __syncthreads();

        // acc += P @ V : all LDS.128.
        #pragma unroll
        for (int kk = 0; kk < 64; kk += 4) {
            float4 pv[4], vv[4];
            #pragma unroll
            for (int i = 0; i < 4; i++)
                pv[i] = *(const float4*)(Ss + (tr * 4 + i) * QS_LD + kk);
            #pragma unroll
            for (int dd = 0; dd < 4; dd++)
                vv[dd] = *(const float4*)(Vs + (kk + dd) * 64 + tc * 4);
            #pragma unroll
            for (int i = 0; i < 4; i++) {
                acc[i][0] += pv[i].x * vv[0].x + pv[i].y * vv[1].x
                           + pv[i].z * vv[2].x + pv[i].w * vv[3].x;
                acc[i][1] += pv[i].x * vv[0].y + pv[i].y * vv[1].y
                           + pv[i].z * vv[2].y + pv[i].w * vv[3].y;
                acc[i][2] += pv[i].x * vv[0].z + pv[i].y * vv[1].z
                           + pv[i].z * vv[2].z + pv[i].w * vv[3].z;
                acc[i][3] += pv[i].x * vv[0].w + pv[i].y * vv[1].w
                           + pv[i].z * vv[2].w + pv[i].w * vv[3].w;
            }
        }
    }

    // Epilogue: normalize, write O[b, sq, h*64 + d] ([B*S, D] row-major).
    #pragma unroll
    for (int i = 0; i < 4; i++) {
        const float inv_l = 1.f / l_run[i];
        const int sq = qt * 64 + tr * 4 + i;
        float4 o;
        o.x = acc[i][0] * inv_l;
        o.y = acc[i][1] * inv_l;
        o.z = acc[i][2] * inv_l;
        o.w = acc[i][3] * inv_l;
        *(float4*)(O + ((size_t)(b * SEQL + sq)) * DIM + h * HD + tc * 4) = o;
    }
}

// ---------------------------------------------------------------------------
// Launch
// ---------------------------------------------------------------------------
extern "C" void kernel_launch(void* const* d_in, const int* in_sizes, int n_in,
                              void* d_out, int out_size)
{
    const float* x    = (const float*)d_in[0];   // [B,S,D]
    const float* Wqkv = (const float*)d_in[1];   // [D, 3D]
    const float* bqkv = (const float*)d_in[2];   // [3D]
    const float* Wout = (const float*)d_in[3];   // [D, D]
    const float* bout = (const float*)d_in[4];   // [D]
    float* out = (float*)d_out;                  // [B,S,D]

    void* p;
    cudaGetSymbolAddress(&p, g_qkv);  float* qkv  = (float*)p;
    cudaGetSymbolAddress(&p, g_q);    float* q    = (float*)p;
    cudaGetSymbolAddress(&p, g_k);    float* k    = (float*)p;
    cudaGetSymbolAddress(&p, g_v);    float* v    = (float*)p;
    cudaGetSymbolAddress(&p, g_attn); float* attn = (float*)p;

    cudaFuncSetAttribute(flash_kernel,
                         cudaFuncAttributeMaxDynamicSharedMemorySize,
                         FLASH_SMEM_BYTES);

    const int M = BATCH * SEQL;   // 8192

    // 1) QKV = x @ Wqkv + bqkv
    sgemm_bias<<<dim3(D3 / 128, M / 128), 256>>>(x, Wqkv, bqkv, qkv, M, D3, DIM);

    // 2) RoPE + split into q,k,v [B,H,S,HD]
    {
        const int total = BATCH * NHEAD * SEQL * 32;
        rope_split_kernel<<<total / 256, 256>>>(qkv, q, k, v);
    }

    // 3) Flash attention -> attn [B*S, D]
    flash_kernel<<<dim3(SEQL / 64, BATCH * NHEAD), 256, FLASH_SMEM_BYTES>>>(
        q, k, v, attn);

    // 4) out = attn @ Wout + bout
    sgemm_bias<<<dim3(DIM / 128, M / 128), 256>>>(attn, Wout, bout, out, M, DIM, DIM);
}

// round 4
// speedup vs baseline: 2.7500x; 2.7319x over previous
#include <cuda_runtime.h>
#include <cuda_bf16.h>
#include <math.h>
#include <stdint.h>

// Problem constants
#define BATCH 4
#define SEQL  2048
#define DIM   1024
#define NHEAD 16
#define HD    64
#define D3    (3*DIM)
#define MROWS (BATCH*SEQL)          // 8192

// ---------------------------------------------------------------------------
// Scratch (static device globals)
// ---------------------------------------------------------------------------
__device__ float        g_qkv[(size_t)MROWS*D3];            // fp32 [B*S, 3D]
__device__ __nv_bfloat16 g_x_hi[(size_t)MROWS*DIM],  g_x_lo[(size_t)MROWS*DIM];
__device__ __nv_bfloat16 g_wqkv_hi[(size_t)DIM*D3],  g_wqkv_lo[(size_t)DIM*D3];
__device__ __nv_bfloat16 g_wout_hi[(size_t)DIM*DIM], g_wout_lo[(size_t)DIM*DIM];
__device__ __nv_bfloat16 g_q_hi[(size_t)MROWS*DIM],  g_q_lo[(size_t)MROWS*DIM];
__device__ __nv_bfloat16 g_k_hi[(size_t)MROWS*DIM],  g_k_lo[(size_t)MROWS*DIM];
__device__ __nv_bfloat16 g_v_hi[(size_t)MROWS*DIM],  g_v_lo[(size_t)MROWS*DIM];
__device__ __nv_bfloat16 g_at_hi[(size_t)MROWS*DIM], g_at_lo[(size_t)MROWS*DIM];

// ---------------------------------------------------------------------------
// MMA helpers
// ---------------------------------------------------------------------------
__device__ __forceinline__ uint32_t smem_u32(const void* p) {
    return (uint32_t)__cvta_generic_to_shared(p);
}
__device__ __forceinline__ void ldsm_x4(uint32_t* r, uint32_t addr) {
    asm volatile("ldmatrix.sync.aligned.m8n8.x4.shared.b16 {%0,%1,%2,%3}, [%4];"
                 : "=r"(r[0]), "=r"(r[1]), "=r"(r[2]), "=r"(r[3]) : "r"(addr));
}
__device__ __forceinline__ void ldsm_x4_t(uint32_t* r, uint32_t addr) {
    asm volatile("ldmatrix.sync.aligned.m8n8.x4.trans.shared.b16 {%0,%1,%2,%3}, [%4];"
                 : "=r"(r[0]), "=r"(r[1]), "=r"(r[2]), "=r"(r[3]) : "r"(addr));
}
__device__ __forceinline__ void mma_bf16(float* c, const uint32_t* a,
                                         uint32_t b0, uint32_t b1) {
    asm volatile(
        "mma.sync.aligned.m16n8k16.row.col.f32.bf16.bf16.f32 "
        "{%0,%1,%2,%3}, {%4,%5,%6,%7}, {%8,%9}, {%0,%1,%2,%3};"
        : "+f"(c[0]), "+f"(c[1]), "+f"(c[2]), "+f"(c[3])
        : "r"(a[0]), "r"(a[1]), "r"(a[2]), "r"(a[3]), "r"(b0), "r"(b1));
}
__device__ __forceinline__ uint32_t pack_bf16x2(float lo_val, float hi_val) {
    __nv_bfloat162 t = __floats2bfloat162_rn(lo_val, hi_val);  // .x=low half
    return *reinterpret_cast<uint32_t*>(&t);
}

// ---------------------------------------------------------------------------
// Split fp32 -> bf16 hi + bf16 lo
// ---------------------------------------------------------------------------
__global__ void split_kernel(const float* __restrict__ src,
                             __nv_bfloat16* __restrict__ hi,
                             __nv_bfloat16* __restrict__ lo, int n)
{
    int i = blockIdx.x * blockDim.x + threadIdx.x;
    if (i < n) {
        float x = src[i];
        __nv_bfloat16 h = __float2bfloat16(x);
        hi[i] = h;
        lo[i] = __float2bfloat16(x - __bfloat162float(h));
    }
}

// ---------------------------------------------------------------------------
// GEMM (tensor core, bf16-split): C[M,N] = A[M,K]B[K,N] + bias
// BM=128 BN=128 BK=32, 256 threads = 8 warps (4x2), warp tile 32x64.
// ---------------------------------------------------------------------------
#define A_LD 40    // smem k-stride for A (bf16): 80B rows -> conflict-free LDSM
#define B_LD 136   // smem n-stride for B: 272B rows -> conflict-free LDSM

__global__ __launch_bounds__(256, 2) void mma_gemm(
    const __nv_bfloat16* __restrict__ Ah, const __nv_bfloat16* __restrict__ Al,
    const __nv_bfloat16* __restrict__ Bh, const __nv_bfloat16* __restrict__ Bl,
    const float* __restrict__ bias, float* __restrict__ C,
    int M, int N, int K)
{
    __shared__ __nv_bfloat16 sAh[128 * A_LD], sAl[128 * A_LD];
    __shared__ __nv_bfloat16 sBh[32 * B_LD],  sBl[32 * B_LD];

    const int tid  = threadIdx.x;
    const int lane = tid & 31;
    const int wid  = tid >> 5;
    const int wm   = wid & 3;          // 0..3 -> m offset wm*32
    const int wn   = wid >> 2;         // 0..1 -> n offset wn*64
    const int m0   = blockIdx.y * 128;
    const int n0   = blockIdx.x * 128;

    float c[2][8][4];
    #pragma unroll
    for (int i = 0; i < 2; i++)
        #pragma unroll
        for (int j = 0; j < 8; j++)
            #pragma unroll
            for (int t = 0; t < 4; t++) c[i][j][t] = 0.f;

    // ldmatrix lane addresses (element offsets within tiles)
    const int a_row = (lane & 15);              // + wm*32 + mi*16
    const int a_col = (lane >> 4) * 8;          // + ks
    const int b_row = ((lane >> 3) & 1) * 8 + (lane & 7);   // + ks
    const int b_col = wn * 64 + (lane >> 4) * 8;            // + nb*16

    for (int k0 = 0; k0 < K; k0 += 32) {
        // ---- load tiles ----
        #pragma unroll
        for (int i = 0; i < 2; i++) {            // A: 512 chunks of 8 bf16
            int ch = tid + i * 256;
            int r = ch >> 2, cc = (ch & 3) * 8;
            const size_t ga = (size_t)(m0 + r) * K + k0 + cc;
            *(uint4*)(&sAh[r * A_LD + cc]) = *(const uint4*)(&Ah[ga]);
            *(uint4*)(&sAl[r * A_LD + cc]) = *(const uint4*)(&Al[ga]);
        }
        #pragma unroll
        for (int i = 0; i < 2; i++) {            // B: 512 chunks
            int ch = tid + i * 256;
            int r = ch >> 4, cc = (ch & 15) * 8;
            const size_t gb = (size_t)(k0 + r) * N + n0 + cc;
            *(uint4*)(&sBh[r * B_LD + cc]) = *(const uint4*)(&Bh[gb]);
            *(uint4*)(&sBl[r * B_LD + cc]) = *(const uint4*)(&Bl[gb]);
        }
        __syncthreads();

        #pragma unroll
        for (int ks = 0; ks < 32; ks += 16) {
            uint32_t ah[2][4], al[2][4];
            #pragma unroll
            for (int mi = 0; mi < 2; mi++) {
                uint32_t off = (uint32_t)((wm * 32 + mi * 16 + a_row) * A_LD
                                          + ks + a_col) * 2u;
                ldsm_x4(ah[mi], smem_u32(sAh) + off);
                ldsm_x4(al[mi], smem_u32(sAl) + off);
            }
            #pragma unroll
            for (int nb = 0; nb < 4; nb++) {
                uint32_t bh[4], bl[4];
                uint32_t off = (uint32_t)((ks + b_row) * B_LD
                                          + nb * 16 + b_col) * 2u;
                ldsm_x4_t(bh, smem_u32(sBh) + off);
                ldsm_x4_t(bl, smem_u32(sBl) + off);
                #pragma unroll
                for (int mi = 0; mi < 2; mi++) {
                    mma_bf16(c[mi][2 * nb],     ah[mi], bh[0], bh[1]);
                    mma_bf16(c[mi][2 * nb],     ah[mi], bl[0], bl[1]);
                    mma_bf16(c[mi][2 * nb],     al[mi], bh[0], bh[1]);
                    mma_bf16(c[mi][2 * nb + 1], ah[mi], bh[2], bh[3]);
                    mma_bf16(c[mi][2 * nb + 1], ah[mi], bl[2], bl[3]);
                    mma_bf16(c[mi][2 * nb + 1], al[mi], bh[2], bh[3]);
                }
            }
        }
        __syncthreads();
    }

    // ---- epilogue ----
    const int gid = lane >> 2, tig = lane & 3;
    #pragma unroll
    for (int mi = 0; mi < 2; mi++) {
        #pragma unroll
        for (int ni = 0; ni < 8; ni++) {
            const int col = n0 + wn * 64 + ni * 8 + tig * 2;
            const int row = m0 + wm * 32 + mi * 16 + gid;
            C[(size_t)row * N + col]           = c[mi][ni][0] + bias[col];
            C[(size_t)row * N + col + 1]       = c[mi][ni][1] + bias[col + 1];
            C[(size_t)(row + 8) * N + col]     = c[mi][ni][2] + bias[col];
            C[(size_t)(row + 8) * N + col + 1] = c[mi][ni][3] + bias[col + 1];
        }
    }
}

// ---------------------------------------------------------------------------
// RoPE + split: qkv fp32 -> q,k (rope) and v, each as bf16 hi/lo, [B,H,S,HD]
// ---------------------------------------------------------------------------
__global__ void rope_split_kernel(const float* __restrict__ qkv,
    __nv_bfloat16* __restrict__ qh, __nv_bfloat16* __restrict__ ql,
    __nv_bfloat16* __restrict__ kh, __nv_bfloat16* __restrict__ kl,
    __nv_bfloat16* __restrict__ vh, __nv_bfloat16* __restrict__ vl)
{
    const int idx = blockIdx.x * blockDim.x + threadIdx.x;
    const int d = idx & 31;
    const int s = (idx >> 5) & (SEQL - 1);
    const int h = (idx >> 16) & (NHEAD - 1);
    const int b = idx >> 20;

    const size_t base = ((size_t)(b * SEQL + s)) * D3 + h * HD;
    const float q1 = qkv[base + d],            q2 = qkv[base + d + 32];
    const float k1 = qkv[base + DIM + d],      k2 = qkv[base + DIM + d + 32];
    const float v1 = qkv[base + 2 * DIM + d],  v2 = qkv[base + 2 * DIM + d + 32];

    const double inv_freq = exp(-log(10000.0) * (double)(2 * d) / (double)HD);
    const double ang = (double)s * inv_freq;
    const float c  = (float)cos(ang);
    const float sn = (float)sin(ang);

    const float qa = q1 * c - q2 * sn, qb = q1 * sn + q2 * c;
    const float ka = k1 * c - k2 * sn, kb = k1 * sn + k2 * c;

    const size_t ob = ((size_t)((b * NHEAD + h) * SEQL + s)) * HD + d;
    __nv_bfloat16 t;
    t = __float2bfloat16(qa); qh[ob] = t;      ql[ob]      = __float2bfloat16(qa - __bfloat162float(t));
    t = __float2bfloat16(qb); qh[ob + 32] = t; ql[ob + 32] = __float2bfloat16(qb - __bfloat162float(t));
    t = __float2bfloat16(ka); kh[ob] = t;      kl[ob]      = __float2bfloat16(ka - __bfloat162float(t));
    t = __float2bfloat16(kb); kh[ob + 32] = t; kl[ob + 32] = __float2bfloat16(kb - __bfloat162float(t));
    t = __float2bfloat16(v1); vh[ob] = t;      vl[ob]      = __float2bfloat16(v1 - __bfloat162float(t));
    t = __float2bfloat16(v2); vh[ob + 32] = t; vl[ob + 32] = __float2bfloat16(v2 - __bfloat162float(t));
}

// ---------------------------------------------------------------------------
// Flash attention (tensor core, bf16-split). CTA = (bh, 64-row q tile),
// 128 threads = 4 warps, each warp owns 16 q rows. Output -> attn bf16 hi/lo.
// ---------------------------------------------------------------------------
#define F_LD 72   // smem d-stride (144B rows -> conflict-free LDSM)

__global__ void flash_mma(
    const __nv_bfloat16* __restrict__ Qh, const __nv_bfloat16* __restrict__ Ql,
    const __nv_bfloat16* __restrict__ Kh, const __nv_bfloat16* __restrict__ Kl,
    const __nv_bfloat16* __restrict__ Vh, const __nv_bfloat16* __restrict__ Vl,
    __nv_bfloat16* __restrict__ Oh, __nv_bfloat16* __restrict__ Ol)
{
    __shared__ __nv_bfloat16 sKh[64 * F_LD], sKl[64 * F_LD];
    __shared__ __nv_bfloat16 sVh[64 * F_LD], sVl[64 * F_LD];

    const int tid  = threadIdx.x;
    const int lane = tid & 31;
    const int w    = tid >> 5;           // warp 0..3 -> q rows w*16..
    const int gid  = lane >> 2, tig = lane & 3;
    const int qt = blockIdx.x, bh = blockIdx.y;
    const int b = bh >> 4, h = bh & 15;

    const size_t qbase = ((size_t)bh * SEQL + (size_t)qt * 64) * HD;
    const size_t kbase = (size_t)bh * SEQL * HD;

    // ---- stage Q tile into sKh/sKl, fragment it, keep in regs ----
    #pragma unroll
    for (int i = 0; i < 4; i++) {
        int ch = tid + i * 128;                 // 512 chunks of 8 bf16
        int r = ch >> 3, cc = (ch & 7) * 8;
        *(uint4*)(&sKh[r * F_LD + cc]) = *(const uint4*)(&Qh[qbase + r * HD + cc]);
        *(uint4*)(&sKl[r * F_LD + cc]) = *(const uint4*)(&Ql[qbase + r * HD + cc]);
    }
    __syncthreads();

    uint32_t qfh[4][4], qfl[4][4];
    {
        const int a_row = w * 16 + (lane & 15);
        const int a_col = (lane >> 4) * 8;
        #pragma unroll
        for (int ks = 0; ks < 4; ks++) {
            uint32_t off = (uint32_t)(a_row * F_LD + ks * 16 + a_col) * 2u;
            ldsm_x4(qfh[ks], smem_u32(sKh) + off);
            ldsm_x4(qfl[ks], smem_u32(sKl) + off);
        }
    }
    __syncthreads();

    float o[8][4];
    #pragma unroll
    for (int i = 0; i < 8; i++)
        #pragma unroll
        for (int t = 0; t < 4; t++) o[i][t] = 0.f;
    float m0 = -1e30f, m1 = -1e30f, l0 = 0.f, l1 = 0.f;
    const float scale = 0.125f;

    // lane address components
    const int kn_row = (lane >> 4) * 8 + (lane & 7);        // token within nb*16
    const int kn_col = ((lane >> 3) & 1) * 8;               // k offset
    const int v_row  = ((lane >> 3) & 1) * 8 + (lane & 7);  // token within t*16
    const int v_col  = (lane >> 4) * 8;                     // d offset

    for (int kt = 0; kt < SEQL / 64; kt++) {
        // ---- load K/V tiles ----
        #pragma unroll
        for (int i = 0; i < 4; i++) {
            int ch = tid + i * 128;
            int r = ch >> 3, cc = (ch & 7) * 8;
            const size_t g = kbase + (size_t)(kt * 64 + r) * HD + cc;
            const int sm = r * F_LD + cc;
            *(uint4*)(&sKh[sm]) = *(const uint4*)(&Kh[g]);
            *(uint4*)(&sKl[sm]) = *(const uint4*)(&Kl[g]);
            *(uint4*)(&sVh[sm]) = *(const uint4*)(&Vh[g]);
            *(uint4*)(&sVl[sm]) = *(const uint4*)(&Vl[g]);
        }
        __syncthreads();

        // ---- S = Q K^T ----
        float s[8][4];
        #pragma unroll
        for (int i = 0; i < 8; i++)
            #pragma unroll
            for (int t = 0; t < 4; t++) s[i][t] = 0.f;

        #pragma unroll
        for (int ks = 0; ks < 4; ks++) {
            #pragma unroll
            for (int nb = 0; nb < 4; nb++) {
                uint32_t kh4[4], kl4[4];
                uint32_t off = (uint32_t)((nb * 16 + kn_row) * F_LD
                                          + ks * 16 + kn_col) * 2u;
                ldsm_x4(kh4, smem_u32(sKh) + off);
                ldsm_x4(kl4, smem_u32(sKl) + off);
                mma_bf16(s[2 * nb],     qfh[ks], kh4[0], kh4[1]);
                mma_bf16(s[2 * nb],     qfh[ks], kl4[0], kl4[1]);
                mma_bf16(s[2 * nb],     qfl[ks], kh4[0], kh4[1]);
                mma_bf16(s[2 * nb + 1], qfh[ks], kh4[2], kh4[3]);
                mma_bf16(s[2 * nb + 1], qfh[ks], kl4[2], kl4[3]);
                mma_bf16(s[2 * nb + 1], qfl[ks], kh4[2], kh4[3]);
            }
        }

        // ---- online softmax (rows gid and gid+8) ----
        float mx0 = -1e30f, mx1 = -1e30f;
        #pragma unroll
        for (int i = 0; i < 8; i++) {
            #pragma unroll
            for (int t = 0; t < 4; t++) s[i][t] *= scale;
            mx0 = fmaxf(mx0, fmaxf(s[i][0], s[i][1]));
            mx1 = fmaxf(mx1, fmaxf(s[i][2], s[i][3]));
        }
        #pragma unroll
        for (int off = 1; off < 4; off <<= 1) {
            mx0 = fmaxf(mx0, __shfl_xor_sync(0xffffffffu, mx0, off));
            mx1 = fmaxf(mx1, __shfl_xor_sync(0xffffffffu, mx1, off));
        }
        const float mn0 = fmaxf(m0, mx0), mn1 = fmaxf(m1, mx1);
        const float f0 = __expf(m0 - mn0), f1 = __expf(m1 - mn1);
        float ls0 = 0.f, ls1 = 0.f;
        #pragma unroll
        for (int i = 0; i < 8; i++) {
            s[i][0] = __expf(s[i][0] - mn0);
            s[i][1] = __expf(s[i][1] - mn0);
            s[i][2] = __expf(s[i][2] - mn1);
            s[i][3] = __expf(s[i][3] - mn1);
            ls0 += s[i][0] + s[i][1];
            ls1 += s[i][2] + s[i][3];
        }
        #pragma unroll
        for (int off = 1; off < 4; off <<= 1) {
            ls0 += __shfl_xor_sync(0xffffffffu, ls0, off);
            ls1 += __shfl_xor_sync(0xffffffffu, ls1, off);
        }
        l0 = l0 * f0 + ls0;  m0 = mn0;
        l1 = l1 * f1 + ls1;  m1 = mn1;
        #pragma unroll
        for (int i = 0; i < 8; i++) {
            o[i][0] *= f0; o[i][1] *= f0;
            o[i][2] *= f1; o[i][3] *= f1;
        }

        // ---- O += P V (P reused in-register as A fragments) ----
        #pragma unroll
        for (int t = 0; t < 4; t++) {
            uint32_t ph[4], pl[4];
            #pragma unroll
            for (int half = 0; half < 2; half++) {
                const float* sj = s[2 * t + half];
                float h0f = __bfloat162float(__float2bfloat16(sj[0]));
                float h1f = __bfloat162float(__float2bfloat16(sj[1]));
                float h2f = __bfloat162float(__float2bfloat16(sj[2]));
                float h3f = __bfloat162float(__float2bfloat16(sj[3]));
                ph[2 * half]     = pack_bf16x2(h0f, h1f);
                ph[2 * half + 1] = pack_bf16x2(h2f, h3f);
                pl[2 * half]     = pack_bf16x2(sj[0] - h0f, sj[1] - h1f);
                pl[2 * half + 1] = pack_bf16x2(sj[2] - h2f, sj[3] - h3f);
            }
            // reorder to A-frag: a0=(gid,k0-7) a1=(gid+8,k0-7) a2=(gid,k8-15) a3=(gid+8,k8-15)
            uint32_t ah[4] = {ph[0], ph[1], ph[2], ph[3]};
            uint32_t al[4] = {pl[0], pl[1], pl[2], pl[3]};
            #pragma unroll
            for (int nb = 0; nb < 4; nb++) {
                uint32_t vh4[4], vl4[4];
                uint32_t off = (uint32_t)((t * 16 + v_row) * F_LD
                                          + nb * 16 + v_col) * 2u;
                ldsm_x4_t(vh4, smem_u32(sVh) + off);
                ldsm_x4_t(vl4, smem_u32(sVl) + off);
                mma_bf16(o[2 * nb],     ah, vh4[0], vh4[1]);
                mma_bf16(o[2 * nb],     ah, vl4[0], vl4[1]);
                mma_bf16(o[2 * nb],     al, vh4[0], vh4[1]);
                mma_bf16(o[2 * nb + 1], ah, vh4[2], vh4[3]);
                mma_bf16(o[2 * nb + 1], ah, vl4[2], vl4[3]);
                mma_bf16(o[2 * nb + 1], al, vh4[2], vh4[3]);
            }
        }
        __syncthreads();
    }

    // ---- epilogue: normalize, split to bf16 hi/lo, write [B*S, D] ----
    const float il0 = 1.f / l0, il1 = 1.f / l1;
    const int sq0 = qt * 64 + w * 16 + gid;
    #pragma unroll
    for (int ni = 0; ni < 8; ni++) {
        const int col = h * HD + ni * 8 + tig * 2;
        {
            float v0 = o[ni][0] * il0, v1 = o[ni][1] * il0;
            float h0f = __bfloat162float(__float2bfloat16(v0));
            float h1f = __bfloat162float(__float2bfloat16(v1));
            uint32_t hp = pack_bf16x2(h0f, h1f);
            uint32_t lp = pack_bf16x2(v0 - h0f, v1 - h1f);
            const size_t a = ((size_t)(b * SEQL + sq0)) * DIM + col;
            *(uint32_t*)(&Oh[a]) = hp;
            *(uint32_t*)(&Ol[a]) = lp;
        }
        {
            float v0 = o[ni][2] * il1, v1 = o[ni][3] * il1;
            float h0f = __bfloat162float(__float2bfloat16(v0));
            float h1f = __bfloat162float(__float2bfloat16(v1));
            uint32_t hp = pack_bf16x2(h0f, h1f);
            uint32_t lp = pack_bf16x2(v0 - h0f, v1 - h1f);
            const size_t a = ((size_t)(b * SEQL + sq0 + 8)) * DIM + col;
            *(uint32_t*)(&Oh[a]) = hp;
            *(uint32_t*)(&Ol[a]) = lp;
        }
    }
}

// ---------------------------------------------------------------------------
// Launch
// ---------------------------------------------------------------------------
extern "C" void kernel_launch(void* const* d_in, const int* in_sizes, int n_in,
                              void* d_out, int out_size)
{
    const float* x    = (const float*)d_in[0];
    const float* Wqkv = (const float*)d_in[1];
    const float* bqkv = (const float*)d_in[2];
    const float* Wout = (const float*)d_in[3];
    const float* bout = (const float*)d_in[4];
    float* out = (float*)d_out;

    void* p;
    cudaGetSymbolAddress(&p, g_qkv);     float* qkv = (float*)p;
    cudaGetSymbolAddress(&p, g_x_hi);    __nv_bfloat16* xh = (__nv_bfloat16*)p;
    cudaGetSymbolAddress(&p, g_x_lo);    __nv_bfloat16* xl = (__nv_bfloat16*)p;
    cudaGetSymbolAddress(&p, g_wqkv_hi); __nv_bfloat16* wqh = (__nv_bfloat16*)p;
    cudaGetSymbolAddress(&p, g_wqkv_lo); __nv_bfloat16* wql = (__nv_bfloat16*)p;
    cudaGetSymbolAddress(&p, g_wout_hi); __nv_bfloat16* woh = (__nv_bfloat16*)p;
    cudaGetSymbolAddress(&p, g_wout_lo); __nv_bfloat16* wol = (__nv_bfloat16*)p;
    cudaGetSymbolAddress(&p, g_q_hi);    __nv_bfloat16* qh = (__nv_bfloat16*)p;
    cudaGetSymbolAddress(&p, g_q_lo);    __nv_bfloat16* ql = (__nv_bfloat16*)p;
    cudaGetSymbolAddress(&p, g_k_hi);    __nv_bfloat16* kh = (__nv_bfloat16*)p;
    cudaGetSymbolAddress(&p, g_k_lo);    __nv_bfloat16* kl = (__nv_bfloat16*)p;
    cudaGetSymbolAddress(&p, g_v_hi);    __nv_bfloat16* vh = (__nv_bfloat16*)p;
    cudaGetSymbolAddress(&p, g_v_lo);    __nv_bfloat16* vl = (__nv_bfloat16*)p;
    cudaGetSymbolAddress(&p, g_at_hi);   __nv_bfloat16* ah = (__nv_bfloat16*)p;
    cudaGetSymbolAddress(&p, g_at_lo);   __nv_bfloat16* al = (__nv_bfloat16*)p;

    // 0) precision splits
    split_kernel<<<(MROWS * DIM) / 256, 256>>>(x, xh, xl, MROWS * DIM);
    split_kernel<<<(DIM * D3) / 256, 256>>>(Wqkv, wqh, wql, DIM * D3);
    split_kernel<<<(DIM * DIM) / 256, 256>>>(Wout, woh, wol, DIM * DIM);

    // 1) QKV projection
    mma_gemm<<<dim3(D3 / 128, MROWS / 128), 256>>>(xh, xl, wqh, wql, bqkv, qkv,
                                                   MROWS, D3, DIM);
    // 2) RoPE + split
    rope_split_kernel<<<(BATCH * NHEAD * SEQL * 32) / 256, 256>>>(
        qkv, qh, ql, kh, kl, vh, vl);

    // 3) flash attention -> attn (bf16 hi/lo)
    flash_mma<<<dim3(SEQL / 64, BATCH * NHEAD), 128>>>(qh, ql, kh, kl, vh, vl,
                                                       ah, al);
    // 4) output projection
    mma_gemm<<<dim3(DIM / 128, MROWS / 128), 256>>>(ah, al, woh, wol, bout, out,
                                                    MROWS, DIM, DIM);
}

// round 6
// speedup vs baseline: 2.8613x; 1.0405x over previous
#include <cuda_runtime.h>
#include <cuda_bf16.h>
#include <math.h>
#include <stdint.h>

// Problem constants
#define BATCH 4
#define SEQL  2048
#define DIM   1024
#define NHEAD 16
#define HD    64
#define D3    (3*DIM)
#define MROWS (BATCH*SEQL)          // 8192

// ---------------------------------------------------------------------------
// Scratch (static device globals)
// ---------------------------------------------------------------------------
__device__ float        g_qkv[(size_t)MROWS*D3];
__device__ __nv_bfloat16 g_x_hi[(size_t)MROWS*DIM],  g_x_lo[(size_t)MROWS*DIM];
__device__ __nv_bfloat16 g_wqkv_hi[(size_t)DIM*D3],  g_wqkv_lo[(size_t)DIM*D3];
__device__ __nv_bfloat16 g_wout_hi[(size_t)DIM*DIM], g_wout_lo[(size_t)DIM*DIM];
__device__ __nv_bfloat16 g_q_hi[(size_t)MROWS*DIM],  g_q_lo[(size_t)MROWS*DIM];
__device__ __nv_bfloat16 g_k_hi[(size_t)MROWS*DIM],  g_k_lo[(size_t)MROWS*DIM];
__device__ __nv_bfloat16 g_v_hi[(size_t)MROWS*DIM],  g_v_lo[(size_t)MROWS*DIM];
__device__ __nv_bfloat16 g_at_hi[(size_t)MROWS*DIM], g_at_lo[(size_t)MROWS*DIM];

// ---------------------------------------------------------------------------
// Helpers
// ---------------------------------------------------------------------------
__device__ __forceinline__ uint32_t smem_u32(const void* p) {
    return (uint32_t)__cvta_generic_to_shared(p);
}
__device__ __forceinline__ void cp16(uint32_t saddr, const void* g) {
    asm volatile("cp.async.cg.shared.global [%0], [%1], 16;"
                 :: "r"(saddr), "l"(g) : "memory");
}
#define CP_COMMIT() asm volatile("cp.async.commit_group;" ::: "memory")
#define CP_WAIT(n)  asm volatile("cp.async.wait_group %0;" :: "n"(n) : "memory")

__device__ __forceinline__ void ldsm_x4(uint32_t* r, uint32_t addr) {
    asm volatile("ldmatrix.sync.aligned.m8n8.x4.shared.b16 {%0,%1,%2,%3}, [%4];"
                 : "=r"(r[0]), "=r"(r[1]), "=r"(r[2]), "=r"(r[3]) : "r"(addr));
}
__device__ __forceinline__ void ldsm_x4_t(uint32_t* r, uint32_t addr) {
    asm volatile("ldmatrix.sync.aligned.m8n8.x4.trans.shared.b16 {%0,%1,%2,%3}, [%4];"
                 : "=r"(r[0]), "=r"(r[1]), "=r"(r[2]), "=r"(r[3]) : "r"(addr));
}
__device__ __forceinline__ void mma_bf16(float* c, const uint32_t* a,
                                         uint32_t b0, uint32_t b1) {
    asm volatile(
        "mma.sync.aligned.m16n8k16.row.col.f32.bf16.bf16.f32 "
        "{%0,%1,%2,%3}, {%4,%5,%6,%7}, {%8,%9}, {%0,%1,%2,%3};"
        : "+f"(c[0]), "+f"(c[1]), "+f"(c[2]), "+f"(c[3])
        : "r"(a[0]), "r"(a[1]), "r"(a[2]), "r"(a[3]), "r"(b0), "r"(b1));
}
__device__ __forceinline__ uint32_t pack_bf16x2(float lo_val, float hi_val) {
    __nv_bfloat162 t = __floats2bfloat162_rn(lo_val, hi_val);
    return *reinterpret_cast<uint32_t*>(&t);
}

// ---------------------------------------------------------------------------
// Split fp32 -> bf16 hi + lo
// ---------------------------------------------------------------------------
__global__ void split_kernel(const float* __restrict__ src,
                             __nv_bfloat16* __restrict__ hi,
                             __nv_bfloat16* __restrict__ lo, int n)
{
    int i = blockIdx.x * blockDim.x + threadIdx.x;
    if (i < n) {
        float x = src[i];
        __nv_bfloat16 h = __float2bfloat16(x);
        hi[i] = h;
        lo[i] = __float2bfloat16(x - __bfloat162float(h));
    }
}

// ---------------------------------------------------------------------------
// GEMM (tensor core, bf16-split, cp.async double-buffered)
// C[M,N] = A[M,K] @ B[K,N] + bias. BM=BN=128, BK=32, 256 thr, warp tile 32x64.
// ---------------------------------------------------------------------------
#define A_LD 40
#define B_LD 136
#define G_AOFF_L 5120            // elements: sAl after sAh (128*40)
#define G_BOFF_H 10240           // sBh
#define G_BOFF_L 14592           // sBl (sBh + 32*136)
#define G_STAGE  18944           // elements per stage
#define G_SMEM_BYTES (2 * G_STAGE * 2)

__global__ __launch_bounds__(256, 2) void mma_gemm(
    const __nv_bfloat16* __restrict__ Ah, const __nv_bfloat16* __restrict__ Al,
    const __nv_bfloat16* __restrict__ Bh, const __nv_bfloat16* __restrict__ Bl,
    const float* __restrict__ bias, float* __restrict__ C,
    int M, int N, int K)
{
    extern __shared__ __nv_bfloat16 gsm[];

    const int tid  = threadIdx.x;
    const int lane = tid & 31;
    const int wid  = tid >> 5;
    const int wm   = wid & 3;
    const int wn   = wid >> 2;
    const int m0   = blockIdx.y * 128;
    const int n0   = blockIdx.x * 128;

    float c[2][8][4];
    #pragma unroll
    for (int i = 0; i < 2; i++)
        #pragma unroll
        for (int j = 0; j < 8; j++)
            #pragma unroll
            for (int t = 0; t < 4; t++) c[i][j][t] = 0.f;

    const int a_row = (lane & 15);
    const int a_col = (lane >> 4) * 8;
    const int b_row = ((lane >> 3) & 1) * 8 + (lane & 7);
    const int b_col = wn * 64 + (lane >> 4) * 8;

    // async stage loader
    auto load_stage = [&](int st, int k0) {
        __nv_bfloat16* sb = gsm + st * G_STAGE;
        #pragma unroll
        for (int i = 0; i < 2; i++) {            // A: 512 16B chunks
            int ch = tid + i * 256;
            int r = ch >> 2, c8 = (ch & 3) * 8;
            const size_t ga = (size_t)(m0 + r) * K + k0 + c8;
            cp16(smem_u32(sb + r * A_LD + c8), Ah + ga);
            cp16(smem_u32(sb + G_AOFF_L + r * A_LD + c8), Al + ga);
        }
        #pragma unroll
        for (int i = 0; i < 2; i++) {            // B: 512 16B chunks
            int ch = tid + i * 256;
            int r = ch >> 4, cc = (ch & 15) * 8;
            const size_t gb = (size_t)(k0 + r) * N + n0 + cc;
            cp16(smem_u32(sb + G_BOFF_H + r * B_LD + cc), Bh + gb);
            cp16(smem_u32(sb + G_BOFF_L + r * B_LD + cc), Bl + gb);
        }
    };

    load_stage(0, 0);
    CP_COMMIT();

    const int NCH = K / 32;
    for (int i = 0; i < NCH; i++) {
        if (i + 1 < NCH) {
            load_stage((i + 1) & 1, (i + 1) * 32);
            CP_COMMIT();
            CP_WAIT(1);
        } else {
            CP_WAIT(0);
        }
        __syncthreads();

        const __nv_bfloat16* sb = gsm + (i & 1) * G_STAGE;
        const uint32_t uAh = smem_u32(sb);
        const uint32_t uAl = smem_u32(sb + G_AOFF_L);
        const uint32_t uBh = smem_u32(sb + G_BOFF_H);
        const uint32_t uBl = smem_u32(sb + G_BOFF_L);

        #pragma unroll
        for (int ks = 0; ks < 32; ks += 16) {
            uint32_t ah[2][4], al[2][4];
            #pragma unroll
            for (int mi = 0; mi < 2; mi++) {
                uint32_t off = (uint32_t)((wm * 32 + mi * 16 + a_row) * A_LD
                                          + ks + a_col) * 2u;
                ldsm_x4(ah[mi], uAh + off);
                ldsm_x4(al[mi], uAl + off);
            }
            #pragma unroll
            for (int nb = 0; nb < 4; nb++) {
                uint32_t bh[4], bl[4];
                uint32_t off = (uint32_t)((ks + b_row) * B_LD
                                          + nb * 16 + b_col) * 2u;
                ldsm_x4_t(bh, uBh + off);
                ldsm_x4_t(bl, uBl + off);
                #pragma unroll
                for (int mi = 0; mi < 2; mi++) {
                    mma_bf16(c[mi][2 * nb],     ah[mi], bh[0], bh[1]);
                    mma_bf16(c[mi][2 * nb],     ah[mi], bl[0], bl[1]);
                    mma_bf16(c[mi][2 * nb],     al[mi], bh[0], bh[1]);
                    mma_bf16(c[mi][2 * nb + 1], ah[mi], bh[2], bh[3]);
                    mma_bf16(c[mi][2 * nb + 1], ah[mi], bl[2], bl[3]);
                    mma_bf16(c[mi][2 * nb + 1], al[mi], bh[2], bh[3]);
                }
            }
        }
        __syncthreads();
    }

    const int gid = lane >> 2, tig = lane & 3;
    #pragma unroll
    for (int mi = 0; mi < 2; mi++) {
        #pragma unroll
        for (int ni = 0; ni < 8; ni++) {
            const int col = n0 + wn * 64 + ni * 8 + tig * 2;
            const int row = m0 + wm * 32 + mi * 16 + gid;
            C[(size_t)row * N + col]           = c[mi][ni][0] + bias[col];
            C[(size_t)row * N + col + 1]       = c[mi][ni][1] + bias[col + 1];
            C[(size_t)(row + 8) * N + col]     = c[mi][ni][2] + bias[col];
            C[(size_t)(row + 8) * N + col + 1] = c[mi][ni][3] + bias[col + 1];
        }
    }
}

// ---------------------------------------------------------------------------
// RoPE + split
// ---------------------------------------------------------------------------
__global__ void rope_split_kernel(const float* __restrict__ qkv,
    __nv_bfloat16* __restrict__ qh, __nv_bfloat16* __restrict__ ql,
    __nv_bfloat16* __restrict__ kh, __nv_bfloat16* __restrict__ kl,
    __nv_bfloat16* __restrict__ vh, __nv_bfloat16* __restrict__ vl)
{
    const int idx = blockIdx.x * blockDim.x + threadIdx.x;
    const int d = idx & 31;
    const int s = (idx >> 5) & (SEQL - 1);
    const int h = (idx >> 16) & (NHEAD - 1);
    const int b = idx >> 20;

    const size_t base = ((size_t)(b * SEQL + s)) * D3 + h * HD;
    const float q1 = qkv[base + d],            q2 = qkv[base + d + 32];
    const float k1 = qkv[base + DIM + d],      k2 = qkv[base + DIM + d + 32];
    const float v1 = qkv[base + 2 * DIM + d],  v2 = qkv[base + 2 * DIM + d + 32];

    const double inv_freq = exp(-log(10000.0) * (double)(2 * d) / (double)HD);
    const double ang = (double)s * inv_freq;
    const float c  = (float)cos(ang);
    const float sn = (float)sin(ang);

    const float qa = q1 * c - q2 * sn, qb = q1 * sn + q2 * c;
    const float ka = k1 * c - k2 * sn, kb = k1 * sn + k2 * c;

    const size_t ob = ((size_t)((b * NHEAD + h) * SEQL + s)) * HD + d;
    __nv_bfloat16 t;
    t = __float2bfloat16(qa); qh[ob] = t;      ql[ob]      = __float2bfloat16(qa - __bfloat162float(t));
    t = __float2bfloat16(qb); qh[ob + 32] = t; ql[ob + 32] = __float2bfloat16(qb - __bfloat162float(t));
    t = __float2bfloat16(ka); kh[ob] = t;      kl[ob]      = __float2bfloat16(ka - __bfloat162float(t));
    t = __float2bfloat16(kb); kh[ob + 32] = t; kl[ob + 32] = __float2bfloat16(kb - __bfloat162float(t));
    t = __float2bfloat16(v1); vh[ob] = t;      vl[ob]      = __float2bfloat16(v1 - __bfloat162float(t));
    t = __float2bfloat16(v2); vh[ob + 32] = t; vl[ob + 32] = __float2bfloat16(v2 - __bfloat162float(t));
}

// ---------------------------------------------------------------------------
// Flash attention (legacy mma, cp.async double-buffered K/V)
// CTA = (bh, 64-row q tile), 128 threads = 4 warps x 16 q rows.
// ---------------------------------------------------------------------------
#define F_LD 72
#define F_ARR   (64 * F_LD)                 // elements per array (4608)
#define F_STAGE (4 * F_ARR)                 // sKh,sKl,sVh,sVl
#define F_SMEM_BYTES (2 * F_STAGE * 2)      // 73728

__global__ __launch_bounds__(128) void flash_mma(
    const __nv_bfloat16* __restrict__ Qh, const __nv_bfloat16* __restrict__ Ql,
    const __nv_bfloat16* __restrict__ Kh, const __nv_bfloat16* __restrict__ Kl,
    const __nv_bfloat16* __restrict__ Vh, const __nv_bfloat16* __restrict__ Vl,
    __nv_bfloat16* __restrict__ Oh, __nv_bfloat16* __restrict__ Ol)
{
    extern __shared__ __nv_bfloat16 fsm[];

    const int tid  = threadIdx.x;
    const int lane = tid & 31;
    const int w    = tid >> 5;
    const int gid  = lane >> 2, tig = lane & 3;
    const int qt = blockIdx.x, bh = blockIdx.y;
    const int b = bh >> 4, h = bh & 15;

    const size_t qbase = ((size_t)bh * SEQL + (size_t)qt * 64) * HD;
    const size_t kbase = (size_t)bh * SEQL * HD;

    // ---- stage Q through stage-0 buffers, fragment to regs ----
    {
        __nv_bfloat16* sQh = fsm;
        __nv_bfloat16* sQl = fsm + F_ARR;
        #pragma unroll
        for (int i = 0; i < 4; i++) {
            int ch = tid + i * 128;
            int r = ch >> 3, cc = (ch & 7) * 8;
            *(uint4*)(&sQh[r * F_LD + cc]) = *(const uint4*)(&Qh[qbase + r * HD + cc]);
            *(uint4*)(&sQl[r * F_LD + cc]) = *(const uint4*)(&Ql[qbase + r * HD + cc]);
        }
    }
    __syncthreads();

    uint32_t qfh[4][4], qfl[4][4];
    {
        const int a_row = w * 16 + (lane & 15);
        const int a_col = (lane >> 4) * 8;
        #pragma unroll
        for (int ks = 0; ks < 4; ks++) {
            uint32_t off = (uint32_t)(a_row * F_LD + ks * 16 + a_col) * 2u;
            ldsm_x4(qfh[ks], smem_u32(fsm) + off);
            ldsm_x4(qfl[ks], smem_u32(fsm + F_ARR) + off);
        }
    }
    __syncthreads();

    float o[8][4];
    #pragma unroll
    for (int i = 0; i < 8; i++)
        #pragma unroll
        for (int t = 0; t < 4; t++) o[i][t] = 0.f;
    float m0 = -1e30f, m1 = -1e30f, l0 = 0.f, l1 = 0.f;
    const float scale = 0.125f;

    const int kn_row = (lane >> 4) * 8 + (lane & 7);
    const int kn_col = ((lane >> 3) & 1) * 8;
    const int v_row  = ((lane >> 3) & 1) * 8 + (lane & 7);
    const int v_col  = (lane >> 4) * 8;

    auto load_stage = [&](int st, int kt) {
        __nv_bfloat16* sb = fsm + st * F_STAGE;
        #pragma unroll
        for (int i = 0; i < 4; i++) {
            int ch = tid + i * 128;
            int r = ch >> 3, cc = (ch & 7) * 8;
            const size_t g = kbase + (size_t)(kt * 64 + r) * HD + cc;
            const uint32_t so = (uint32_t)(r * F_LD + cc);
            cp16(smem_u32(sb + so),             Kh + g);
            cp16(smem_u32(sb + F_ARR + so),     Kl + g);
            cp16(smem_u32(sb + 2 * F_ARR + so), Vh + g);
            cp16(smem_u32(sb + 3 * F_ARR + so), Vl + g);
        }
    };

    load_stage(0, 0);
    CP_COMMIT();

    const int NKT = SEQL / 64;
    for (int kt = 0; kt < NKT; kt++) {
        if (kt + 1 < NKT) {
            load_stage((kt + 1) & 1, kt + 1);
            CP_COMMIT();
            CP_WAIT(1);
        } else {
            CP_WAIT(0);
        }
        __syncthreads();

        const __nv_bfloat16* sb = fsm + (kt & 1) * F_STAGE;
        const uint32_t uKh = smem_u32(sb);
        const uint32_t uKl = smem_u32(sb + F_ARR);
        const uint32_t uVh = smem_u32(sb + 2 * F_ARR);
        const uint32_t uVl = smem_u32(sb + 3 * F_ARR);

        // ---- S = Q K^T ----
        float s[8][4];
        #pragma unroll
        for (int i = 0; i < 8; i++)
            #pragma unroll
            for (int t = 0; t < 4; t++) s[i][t] = 0.f;

        #pragma unroll
        for (int ks = 0; ks < 4; ks++) {
            #pragma unroll
            for (int nb = 0; nb < 4; nb++) {
                uint32_t kh4[4], kl4[4];
                uint32_t off = (uint32_t)((nb * 16 + kn_row) * F_LD
                                          + ks * 16 + kn_col) * 2u;
                ldsm_x4(kh4, uKh + off);
                ldsm_x4(kl4, uKl + off);
                mma_bf16(s[2 * nb],     qfh[ks], kh4[0], kh4[1]);
                mma_bf16(s[2 * nb],     qfh[ks], kl4[0], kl4[1]);
                mma_bf16(s[2 * nb],     qfl[ks], kh4[0], kh4[1]);
                mma_bf16(s[2 * nb + 1], qfh[ks], kh4[2], kh4[3]);
                mma_bf16(s[2 * nb + 1], qfh[ks], kl4[2], kl4[3]);
                mma_bf16(s[2 * nb + 1], qfl[ks], kh4[2], kh4[3]);
            }
        }

        // ---- online softmax ----
        float mx0 = -1e30f, mx1 = -1e30f;
        #pragma unroll
        for (int i = 0; i < 8; i++) {
            #pragma unroll
            for (int t = 0; t < 4; t++) s[i][t] *= scale;
            mx0 = fmaxf(mx0, fmaxf(s[i][0], s[i][1]));
            mx1 = fmaxf(mx1, fmaxf(s[i][2], s[i][3]));
        }
        #pragma unroll
        for (int off = 1; off < 4; off <<= 1) {
            mx0 = fmaxf(mx0, __shfl_xor_sync(0xffffffffu, mx0, off));
            mx1 = fmaxf(mx1, __shfl_xor_sync(0xffffffffu, mx1, off));
        }
        const float mn0 = fmaxf(m0, mx0), mn1 = fmaxf(m1, mx1);
        const float f0 = __expf(m0 - mn0), f1 = __expf(m1 - mn1);
        float ls0 = 0.f, ls1 = 0.f;
        #pragma unroll
        for (int i = 0; i < 8; i++) {
            s[i][0] = __expf(s[i][0] - mn0);
            s[i][1] = __expf(s[i][1] - mn0);
            s[i][2] = __expf(s[i][2] - mn1);
            s[i][3] = __expf(s[i][3] - mn1);
            ls0 += s[i][0] + s[i][1];
            ls1 += s[i][2] + s[i][3];
        }
        #pragma unroll
        for (int off = 1; off < 4; off <<= 1) {
            ls0 += __shfl_xor_sync(0xffffffffu, ls0, off);
            ls1 += __shfl_xor_sync(0xffffffffu, ls1, off);
        }
        l0 = l0 * f0 + ls0;  m0 = mn0;
        l1 = l1 * f1 + ls1;  m1 = mn1;
        #pragma unroll
        for (int i = 0; i < 8; i++) {
            o[i][0] *= f0; o[i][1] *= f0;
            o[i][2] *= f1; o[i][3] *= f1;
        }

        // ---- O += P V ----
        #pragma unroll
        for (int t = 0; t < 4; t++) {
            uint32_t ah[4], al[4];
            #pragma unroll
            for (int half = 0; half < 2; half++) {
                const float* sj = s[2 * t + half];
                float h0f = __bfloat162float(__float2bfloat16(sj[0]));
                float h1f = __bfloat162float(__float2bfloat16(sj[1]));
                float h2f = __bfloat162float(__float2bfloat16(sj[2]));
                float h3f = __bfloat162float(__float2bfloat16(sj[3]));
                ah[2 * half]     = pack_bf16x2(h0f, h1f);
                ah[2 * half + 1] = pack_bf16x2(h2f, h3f);
                al[2 * half]     = pack_bf16x2(sj[0] - h0f, sj[1] - h1f);
                al[2 * half + 1] = pack_bf16x2(sj[2] - h2f, sj[3] - h3f);
            }
            #pragma unroll
            for (int nb = 0; nb < 4; nb++) {
                uint32_t vh4[4], vl4[4];
                uint32_t off = (uint32_t)((t * 16 + v_row) * F_LD
                                          + nb * 16 + v_col) * 2u;
                ldsm_x4_t(vh4, uVh + off);
                ldsm_x4_t(vl4, uVl + off);
                mma_bf16(o[2 * nb],     ah, vh4[0], vh4[1]);
                mma_bf16(o[2 * nb],     ah, vl4[0], vl4[1]);
                mma_bf16(o[2 * nb],     al, vh4[0], vh4[1]);
                mma_bf16(o[2 * nb + 1], ah, vh4[2], vh4[3]);
                mma_bf16(o[2 * nb + 1], ah, vl4[2], vl4[3]);
                mma_bf16(o[2 * nb + 1], al, vh4[2], vh4[3]);
            }
        }
        __syncthreads();
    }

    // ---- epilogue ----
    const float il0 = 1.f / l0, il1 = 1.f / l1;
    const int sq0 = qt * 64 + w * 16 + gid;
    #pragma unroll
    for (int ni = 0; ni < 8; ni++) {
        const int col = h * HD + ni * 8 + tig * 2;
        {
            float v0 = o[ni][0] * il0, v1 = o[ni][1] * il0;
            float h0f = __bfloat162float(__float2bfloat16(v0));
            float h1f = __bfloat162float(__float2bfloat16(v1));
            const size_t a = ((size_t)(b * SEQL + sq0)) * DIM + col;
            *(uint32_t*)(&Oh[a]) = pack_bf16x2(h0f, h1f);
            *(uint32_t*)(&Ol[a]) = pack_bf16x2(v0 - h0f, v1 - h1f);
        }
        {
            float v0 = o[ni][2] * il1, v1 = o[ni][3] * il1;
            float h0f = __bfloat162float(__float2bfloat16(v0));
            float h1f = __bfloat162float(__float2bfloat16(v1));
            const size_t a = ((size_t)(b * SEQL + sq0 + 8)) * DIM + col;
            *(uint32_t*)(&Oh[a]) = pack_bf16x2(h0f, h1f);
            *(uint32_t*)(&Ol[a]) = pack_bf16x2(v0 - h0f, v1 - h1f);
        }
    }
}

// ---------------------------------------------------------------------------
// Launch
// ---------------------------------------------------------------------------
extern "C" void kernel_launch(void* const* d_in, const int* in_sizes, int n_in,
                              void* d_out, int out_size)
{
    const float* x    = (const float*)d_in[0];
    const float* Wqkv = (const float*)d_in[1];
    const float* bqkv = (const float*)d_in[2];
    const float* Wout = (const float*)d_in[3];
    const float* bout = (const float*)d_in[4];
    float* out = (float*)d_out;

    void* p;
    cudaGetSymbolAddress(&p, g_qkv);     float* qkv = (float*)p;
    cudaGetSymbolAddress(&p, g_x_hi);    __nv_bfloat16* xh = (__nv_bfloat16*)p;
    cudaGetSymbolAddress(&p, g_x_lo);    __nv_bfloat16* xl = (__nv_bfloat16*)p;
    cudaGetSymbolAddress(&p, g_wqkv_hi); __nv_bfloat16* wqh = (__nv_bfloat16*)p;
    cudaGetSymbolAddress(&p, g_wqkv_lo); __nv_bfloat16* wql = (__nv_bfloat16*)p;
    cudaGetSymbolAddress(&p, g_wout_hi); __nv_bfloat16* woh = (__nv_bfloat16*)p;
    cudaGetSymbolAddress(&p, g_wout_lo); __nv_bfloat16* wol = (__nv_bfloat16*)p;
    cudaGetSymbolAddress(&p, g_q_hi);    __nv_bfloat16* qh = (__nv_bfloat16*)p;
    cudaGetSymbolAddress(&p, g_q_lo);    __nv_bfloat16* ql = (__nv_bfloat16*)p;
    cudaGetSymbolAddress(&p, g_k_hi);    __nv_bfloat16* kh = (__nv_bfloat16*)p;
    cudaGetSymbolAddress(&p, g_k_lo);    __nv_bfloat16* kl = (__nv_bfloat16*)p;
    cudaGetSymbolAddress(&p, g_v_hi);    __nv_bfloat16* vh = (__nv_bfloat16*)p;
    cudaGetSymbolAddress(&p, g_v_lo);    __nv_bfloat16* vl = (__nv_bfloat16*)p;
    cudaGetSymbolAddress(&p, g_at_hi);   __nv_bfloat16* ah = (__nv_bfloat16*)p;
    cudaGetSymbolAddress(&p, g_at_lo);   __nv_bfloat16* al = (__nv_bfloat16*)p;

    cudaFuncSetAttribute(mma_gemm, cudaFuncAttributeMaxDynamicSharedMemorySize,
                         G_SMEM_BYTES);
    cudaFuncSetAttribute(flash_mma, cudaFuncAttributeMaxDynamicSharedMemorySize,
                         F_SMEM_BYTES);

    // 0) precision splits
    split_kernel<<<(MROWS * DIM) / 256, 256>>>(x, xh, xl, MROWS * DIM);
    split_kernel<<<(DIM * D3) / 256, 256>>>(Wqkv, wqh, wql, DIM * D3);
    split_kernel<<<(DIM * DIM) / 256, 256>>>(Wout, woh, wol, DIM * DIM);

    // 1) QKV projection
    mma_gemm<<<dim3(D3 / 128, MROWS / 128), 256, G_SMEM_BYTES>>>(
        xh, xl, wqh, wql, bqkv, qkv, MROWS, D3, DIM);

    // 2) RoPE + split
    rope_split_kernel<<<(BATCH * NHEAD * SEQL * 32) / 256, 256>>>(
        qkv, qh, ql, kh, kl, vh, vl);

    // 3) flash attention
    flash_mma<<<dim3(SEQL / 64, BATCH * NHEAD), 128, F_SMEM_BYTES>>>(
        qh, ql, kh, kl, vh, vl, ah, al);

    // 4) output projection
    mma_gemm<<<dim3(DIM / 128, MROWS / 128), 256, G_SMEM_BYTES>>>(
        ah, al, woh, wol, bout, out, MROWS, DIM, DIM);
}

// round 7
// speedup vs baseline: 2.9159x; 1.0191x over previous
#include <cuda_runtime.h>
#include <cuda_bf16.h>
#include <math.h>
#include <stdint.h>

// Problem constants
#define BATCH 4
#define SEQL  2048
#define DIM   1024
#define NHEAD 16
#define HD    64
#define D3    (3*DIM)
#define MROWS (BATCH*SEQL)          // 8192

// ---------------------------------------------------------------------------
// Scratch
// ---------------------------------------------------------------------------
__device__ __nv_bfloat16 g_x_hi[(size_t)MROWS*DIM],  g_x_lo[(size_t)MROWS*DIM];
__device__ __nv_bfloat16 g_wqkv_hi[(size_t)DIM*D3],  g_wqkv_lo[(size_t)DIM*D3];
__device__ __nv_bfloat16 g_wout_hi[(size_t)DIM*DIM], g_wout_lo[(size_t)DIM*DIM];
__device__ __nv_bfloat16 g_q_hi[(size_t)MROWS*DIM],  g_q_lo[(size_t)MROWS*DIM];
__device__ __nv_bfloat16 g_k_hi[(size_t)MROWS*DIM],  g_k_lo[(size_t)MROWS*DIM];
__device__ __nv_bfloat16 g_v_hi[(size_t)MROWS*DIM],  g_v_lo[(size_t)MROWS*DIM];
__device__ __nv_bfloat16 g_at_hi[(size_t)MROWS*DIM], g_at_lo[(size_t)MROWS*DIM];
__device__ float g_cos[SEQL*32], g_sin[SEQL*32];

// ---------------------------------------------------------------------------
// Helpers
// ---------------------------------------------------------------------------
__device__ __forceinline__ uint32_t smem_u32(const void* p) {
    return (uint32_t)__cvta_generic_to_shared(p);
}
__device__ __forceinline__ void cp16(uint32_t saddr, const void* g) {
    asm volatile("cp.async.cg.shared.global [%0], [%1], 16;"
                 :: "r"(saddr), "l"(g) : "memory");
}
#define CP_COMMIT() asm volatile("cp.async.commit_group;" ::: "memory")
#define CP_WAIT(n)  asm volatile("cp.async.wait_group %0;" :: "n"(n) : "memory")

__device__ __forceinline__ void ldsm_x4(uint32_t* r, uint32_t addr) {
    asm volatile("ldmatrix.sync.aligned.m8n8.x4.shared.b16 {%0,%1,%2,%3}, [%4];"
                 : "=r"(r[0]), "=r"(r[1]), "=r"(r[2]), "=r"(r[3]) : "r"(addr));
}
__device__ __forceinline__ void ldsm_x4_t(uint32_t* r, uint32_t addr) {
    asm volatile("ldmatrix.sync.aligned.m8n8.x4.trans.shared.b16 {%0,%1,%2,%3}, [%4];"
                 : "=r"(r[0]), "=r"(r[1]), "=r"(r[2]), "=r"(r[3]) : "r"(addr));
}
__device__ __forceinline__ void mma_bf16(float* c, const uint32_t* a,
                                         uint32_t b0, uint32_t b1) {
    asm volatile(
        "mma.sync.aligned.m16n8k16.row.col.f32.bf16.bf16.f32 "
        "{%0,%1,%2,%3}, {%4,%5,%6,%7}, {%8,%9}, {%0,%1,%2,%3};"
        : "+f"(c[0]), "+f"(c[1]), "+f"(c[2]), "+f"(c[3])
        : "r"(a[0]), "r"(a[1]), "r"(a[2]), "r"(a[3]), "r"(b0), "r"(b1));
}
__device__ __forceinline__ uint32_t pack_bf16x2(float lo_val, float hi_val) {
    __nv_bfloat162 t = __floats2bfloat162_rn(lo_val, hi_val);
    return *reinterpret_cast<uint32_t*>(&t);
}
__device__ __forceinline__ void split2(float a, float b, uint32_t& hp, uint32_t& lp) {
    float ha = __bfloat162float(__float2bfloat16(a));
    float hb = __bfloat162float(__float2bfloat16(b));
    hp = pack_bf16x2(ha, hb);
    lp = pack_bf16x2(a - ha, b - hb);
}

// ---------------------------------------------------------------------------
// Small prep kernels
// ---------------------------------------------------------------------------
__global__ void split_kernel(const float* __restrict__ src,
                             __nv_bfloat16* __restrict__ hi,
                             __nv_bfloat16* __restrict__ lo, int n)
{
    int i = blockIdx.x * blockDim.x + threadIdx.x;
    if (i < n) {
        float x = src[i];
        __nv_bfloat16 h = __float2bfloat16(x);
        hi[i] = h;
        lo[i] = __float2bfloat16(x - __bfloat162float(h));
    }
}

__global__ void rope_table_kernel(float* __restrict__ ct, float* __restrict__ st)
{
    int i = blockIdx.x * blockDim.x + threadIdx.x;   // s*32 + d
    const int d = i & 31, s = i >> 5;
    const double inv_freq = exp(-log(10000.0) * (double)(2 * d) / (double)HD);
    const double ang = (double)s * inv_freq;
    ct[i] = (float)cos(ang);
    st[i] = (float)sin(ang);
}

// ---------------------------------------------------------------------------
// Shared GEMM mainloop config (BM=BN=128, BK=32, 256 thr, warp tile 32x64)
// ---------------------------------------------------------------------------
#define A_LD 40
#define B_LD 136
#define G_AOFF_L 5120
#define G_BOFF_H 10240
#define G_BOFF_L 14592
#define G_STAGE  18944
#define G_SMEM_BYTES (2 * G_STAGE * 2)

#define GEMM_MAINLOOP(Ah, Al, Bh, Bl, K, N)                                     \
    float c[2][8][4];                                                           \
    _Pragma("unroll")                                                           \
    for (int i = 0; i < 2; i++)                                                 \
        _Pragma("unroll")                                                       \
        for (int j = 0; j < 8; j++)                                             \
            _Pragma("unroll")                                                   \
            for (int t = 0; t < 4; t++) c[i][j][t] = 0.f;                       \
    const int a_row = (lane & 15);                                              \
    const int a_col = (lane >> 4) * 8;                                          \
    const int b_row = ((lane >> 3) & 1) * 8 + (lane & 7);                       \
    const int b_col = wn * 64 + (lane >> 4) * 8;                                \
    auto load_stage = [&](int st, int k0) {                                     \
        __nv_bfloat16* sb = gsm + st * G_STAGE;                                 \
        _Pragma("unroll")                                                       \
        for (int i = 0; i < 2; i++) {                                           \
            int ch = tid + i * 256;                                             \
            int r = ch >> 2, c8 = (ch & 3) * 8;                                 \
            const size_t ga = (size_t)(m0 + r) * K + k0 + c8;                   \
            cp16(smem_u32(sb + r * A_LD + c8), Ah + ga);                        \
            cp16(smem_u32(sb + G_AOFF_L + r * A_LD + c8), Al + ga);             \
        }                                                                       \
        _Pragma("unroll")                                                       \
        for (int i = 0; i < 2; i++) {                                           \
            int ch = tid + i * 256;                                             \
            int r = ch >> 4, cc = (ch & 15) * 8;                                \
            const size_t gb = (size_t)(k0 + r) * N + n0 + cc;                   \
            cp16(smem_u32(sb + G_BOFF_H + r * B_LD + cc), Bh + gb);             \
            cp16(smem_u32(sb + G_BOFF_L + r * B_LD + cc), Bl + gb);             \
        }                                                                       \
    };                                                                          \
    load_stage(0, 0);                                                           \
    CP_COMMIT();                                                                \
    const int NCH = K / 32;                                                     \
    for (int i = 0; i < NCH; i++) {                                             \
        if (i + 1 < NCH) {                                                      \
            load_stage((i + 1) & 1, (i + 1) * 32);                              \
            CP_COMMIT();                                                        \
            CP_WAIT(1);                                                         \
        } else {                                                                \
            CP_WAIT(0);                                                         \
        }                                                                       \
        __syncthreads();                                                        \
        const __nv_bfloat16* sb = gsm + (i & 1) * G_STAGE;                      \
        const uint32_t uAh = smem_u32(sb);                                      \
        const uint32_t uAl = smem_u32(sb + G_AOFF_L);                           \
        const uint32_t uBh = smem_u32(sb + G_BOFF_H);                           \
        const uint32_t uBl = smem_u32(sb + G_BOFF_L);                           \
        _Pragma("unroll")                                                       \
        for (int ks = 0; ks < 32; ks += 16) {                                   \
            uint32_t ah[2][4], al[2][4];                                        \
            _Pragma("unroll")                                                   \
            for (int mi = 0; mi < 2; mi++) {                                    \
                uint32_t off = (uint32_t)((wm * 32 + mi * 16 + a_row) * A_LD    \
                                          + ks + a_col) * 2u;                   \
                ldsm_x4(ah[mi], uAh + off);                                     \
                ldsm_x4(al[mi], uAl + off);                                     \
            }                                                                   \
            _Pragma("unroll")                                                   \
            for (int nb = 0; nb < 4; nb++) {                                    \
                uint32_t bh[4], bl[4];                                          \
                uint32_t off = (uint32_t)((ks + b_row) * B_LD                   \
                                          + nb * 16 + b_col) * 2u;              \
                ldsm_x4_t(bh, uBh + off);                                       \
                ldsm_x4_t(bl, uBl + off);                                       \
                _Pragma("unroll")                                               \
                for (int mi = 0; mi < 2; mi++) {                                \
                    mma_bf16(c[mi][2 * nb],     ah[mi], bh[0], bh[1]);          \
                    mma_bf16(c[mi][2 * nb],     ah[mi], bl[0], bl[1]);          \
                    mma_bf16(c[mi][2 * nb],     al[mi], bh[0], bh[1]);          \
                    mma_bf16(c[mi][2 * nb + 1], ah[mi], bh[2], bh[3]);          \
                    mma_bf16(c[mi][2 * nb + 1], ah[mi], bl[2], bl[3]);          \
                    mma_bf16(c[mi][2 * nb + 1], al[mi], bh[2], bh[3]);          \
                }                                                               \
            }                                                                   \
        }                                                                       \
        __syncthreads();                                                        \
    }

// ---------------------------------------------------------------------------
// QKV GEMM with fused bias + RoPE + bf16 split epilogue.
// Writes q/k/v hi/lo in [B,H,S,HD] layout. N = 3072 fixed.
// ---------------------------------------------------------------------------
__global__ __launch_bounds__(256, 2) void gemm_qkv_rope(
    const __nv_bfloat16* __restrict__ Ah, const __nv_bfloat16* __restrict__ Al,
    const __nv_bfloat16* __restrict__ Bh, const __nv_bfloat16* __restrict__ Bl,
    const float* __restrict__ bias,
    const float* __restrict__ ctab, const float* __restrict__ stab,
    __nv_bfloat16* __restrict__ qh, __nv_bfloat16* __restrict__ ql,
    __nv_bfloat16* __restrict__ kh, __nv_bfloat16* __restrict__ kl,
    __nv_bfloat16* __restrict__ vh, __nv_bfloat16* __restrict__ vl)
{
    extern __shared__ __nv_bfloat16 gsm[];
    const int tid  = threadIdx.x;
    const int lane = tid & 31;
    const int wid  = tid >> 5;
    const int wm   = wid & 3;
    const int wn   = wid >> 2;
    const int m0   = blockIdx.y * 128;
    const int n0   = blockIdx.x * 128;

    GEMM_MAINLOOP(Ah, Al, Bh, Bl, DIM, D3)

    // ---- fused epilogue: bias + RoPE + split -> [B,H,S,HD] hi/lo ----
    const int gid = lane >> 2, tig = lane & 3;
    const int ncw = n0 + wn * 64;            // warp col base (64-aligned)
    const int sec = ncw >> 10;               // 0=q 1=k 2=v (uniform per warp)
    const int hh  = (ncw & 1023) >> 6;       // head (uniform per warp)
    __nv_bfloat16* dh = (sec == 0) ? qh : (sec == 1) ? kh : vh;
    __nv_bfloat16* dl = (sec == 0) ? ql : (sec == 1) ? kl : vl;

    #pragma unroll
    for (int mi = 0; mi < 2; mi++) {
        #pragma unroll
        for (int rr = 0; rr < 2; rr++) {
            const int r = m0 + wm * 32 + mi * 16 + gid + rr * 8;
            const int s = r & (SEQL - 1), bb = r >> 11;
            const size_t obase = ((size_t)((bb * NHEAD + hh) * SEQL + s)) * HD;
            #pragma unroll
            for (int ni = 0; ni < 4; ni++) {
                const int d0 = ni * 8 + tig * 2;          // [0,32)
                const int nc = ncw + d0;
                float q1a = c[mi][ni][rr * 2 + 0]     + bias[nc];
                float q1b = c[mi][ni][rr * 2 + 1]     + bias[nc + 1];
                float q2a = c[mi][ni + 4][rr * 2 + 0] + bias[nc + 32];
                float q2b = c[mi][ni + 4][rr * 2 + 1] + bias[nc + 33];
                float oa0, oa1, ob0, ob1;
                if (sec < 2) {
                    const float ca = ctab[s * 32 + d0], cb = ctab[s * 32 + d0 + 1];
                    const float sa = stab[s * 32 + d0], sb2 = stab[s * 32 + d0 + 1];
                    oa0 = q1a * ca - q2a * sa;  ob0 = q1a * sa + q2a * ca;
                    oa1 = q1b * cb - q2b * sb2; ob1 = q1b * sb2 + q2b * cb;
                } else {
                    oa0 = q1a; oa1 = q1b; ob0 = q2a; ob1 = q2b;
                }
                uint32_t hp, lp;
                split2(oa0, oa1, hp, lp);
                *(uint32_t*)(&dh[obase + d0])      = hp;
                *(uint32_t*)(&dl[obase + d0])      = lp;
                split2(ob0, ob1, hp, lp);
                *(uint32_t*)(&dh[obase + d0 + 32]) = hp;
                *(uint32_t*)(&dl[obase + d0 + 32]) = lp;
            }
        }
    }
}

// ---------------------------------------------------------------------------
// Generic GEMM (out projection): fp32 C = A@B + bias
// ---------------------------------------------------------------------------
__global__ __launch_bounds__(256, 2) void mma_gemm(
    const __nv_bfloat16* __restrict__ Ah, const __nv_bfloat16* __restrict__ Al,
    const __nv_bfloat16* __restrict__ Bh, const __nv_bfloat16* __restrict__ Bl,
    const float* __restrict__ bias, float* __restrict__ C,
    int M, int N, int K)
{
    extern __shared__ __nv_bfloat16 gsm[];
    const int tid  = threadIdx.x;
    const int lane = tid & 31;
    const int wid  = tid >> 5;
    const int wm   = wid & 3;
    const int wn   = wid >> 2;
    const int m0   = blockIdx.y * 128;
    const int n0   = blockIdx.x * 128;

    GEMM_MAINLOOP(Ah, Al, Bh, Bl, K, N)

    const int gid = lane >> 2, tig = lane & 3;
    #pragma unroll
    for (int mi = 0; mi < 2; mi++) {
        #pragma unroll
        for (int ni = 0; ni < 8; ni++) {
            const int col = n0 + wn * 64 + ni * 8 + tig * 2;
            const int row = m0 + wm * 32 + mi * 16 + gid;
            C[(size_t)row * N + col]           = c[mi][ni][0] + bias[col];
            C[(size_t)row * N + col + 1]       = c[mi][ni][1] + bias[col + 1];
            C[(size_t)(row + 8) * N + col]     = c[mi][ni][2] + bias[col];
            C[(size_t)(row + 8) * N + col + 1] = c[mi][ni][3] + bias[col + 1];
        }
    }
}

// ---------------------------------------------------------------------------
// Flash attention: 128-row q tiles, 256 threads (8 warps x 16 rows),
// cp.async double-buffered K/V (64-token tiles).
// ---------------------------------------------------------------------------
#define F_LD 72
#define F_ARR   (64 * F_LD)
#define F_STAGE (4 * F_ARR)
#define F_SMEM_BYTES (2 * F_STAGE * 2)      // 73728

__global__ __launch_bounds__(256) void flash_mma(
    const __nv_bfloat16* __restrict__ Qh, const __nv_bfloat16* __restrict__ Ql,
    const __nv_bfloat16* __restrict__ Kh, const __nv_bfloat16* __restrict__ Kl,
    const __nv_bfloat16* __restrict__ Vh, const __nv_bfloat16* __restrict__ Vl,
    __nv_bfloat16* __restrict__ Oh, __nv_bfloat16* __restrict__ Ol)
{
    extern __shared__ __nv_bfloat16 fsm[];

    const int tid  = threadIdx.x;
    const int lane = tid & 31;
    const int w    = tid >> 5;               // warp 0..7 -> q rows w*16..
    const int gid  = lane >> 2, tig = lane & 3;
    const int qt = blockIdx.x, bh = blockIdx.y;
    const int b = bh >> 4, h = bh & 15;

    const size_t qbase = ((size_t)bh * SEQL + (size_t)qt * 128) * HD;
    const size_t kbase = (size_t)bh * SEQL * HD;

    // ---- stage Q (128x64 hi+lo) through stage-0 area, fragment to regs ----
    {
        __nv_bfloat16* sQh = fsm;                 // 128 x F_LD
        __nv_bfloat16* sQl = fsm + 128 * F_LD;
        #pragma unroll
        for (int i = 0; i < 4; i++) {
            int ch = tid + i * 256;               // 1024 chunks
            int r = ch >> 3, cc = (ch & 7) * 8;
            *(uint4*)(&sQh[r * F_LD + cc]) = *(const uint4*)(&Qh[qbase + r * HD + cc]);
            *(uint4*)(&sQl[r * F_LD + cc]) = *(const uint4*)(&Ql[qbase + r * HD + cc]);
        }
    }
    __syncthreads();

    uint32_t qfh[4][4], qfl[4][4];
    {
        const int a_row = w * 16 + (lane & 15);
        const int a_col = (lane >> 4) * 8;
        #pragma unroll
        for (int ks = 0; ks < 4; ks++) {
            uint32_t off = (uint32_t)(a_row * F_LD + ks * 16 + a_col) * 2u;
            ldsm_x4(qfh[ks], smem_u32(fsm) + off);
            ldsm_x4(qfl[ks], smem_u32(fsm + 128 * F_LD) + off);
        }
    }
    __syncthreads();

    float o[8][4];
    #pragma unroll
    for (int i = 0; i < 8; i++)
        #pragma unroll
        for (int t = 0; t < 4; t++) o[i][t] = 0.f;
    float m0 = -1e30f, m1 = -1e30f, l0 = 0.f, l1 = 0.f;
    const float scale = 0.125f;

    const int kn_row = (lane >> 4) * 8 + (lane & 7);
    const int kn_col = ((lane >> 3) & 1) * 8;
    const int v_row  = ((lane >> 3) & 1) * 8 + (lane & 7);
    const int v_col  = (lane >> 4) * 8;

    auto load_stage = [&](int st, int kt) {
        __nv_bfloat16* sb = fsm + st * F_STAGE;
        #pragma unroll
        for (int i = 0; i < 2; i++) {
            int ch = tid + i * 256;               // 512 chunks per array
            int r = ch >> 3, cc = (ch & 7) * 8;
            const size_t g = kbase + (size_t)(kt * 64 + r) * HD + cc;
            const uint32_t so = (uint32_t)(r * F_LD + cc);
            cp16(smem_u32(sb + so),             Kh + g);
            cp16(smem_u32(sb + F_ARR + so),     Kl + g);
            cp16(smem_u32(sb + 2 * F_ARR + so), Vh + g);
            cp16(smem_u32(sb + 3 * F_ARR + so), Vl + g);
        }
    };

    load_stage(0, 0);
    CP_COMMIT();

    const int NKT = SEQL / 64;
    for (int kt = 0; kt < NKT; kt++) {
        if (kt + 1 < NKT) {
            load_stage((kt + 1) & 1, kt + 1);
            CP_COMMIT();
            CP_WAIT(1);
        } else {
            CP_WAIT(0);
        }
        __syncthreads();

        const __nv_bfloat16* sb = fsm + (kt & 1) * F_STAGE;
        const uint32_t uKh = smem_u32(sb);
        const uint32_t uKl = smem_u32(sb + F_ARR);
        const uint32_t uVh = smem_u32(sb + 2 * F_ARR);
        const uint32_t uVl = smem_u32(sb + 3 * F_ARR);

        // ---- S = Q K^T ----
        float s[8][4];
        #pragma unroll
        for (int i = 0; i < 8; i++)
            #pragma unroll
            for (int t = 0; t < 4; t++) s[i][t] = 0.f;

        #pragma unroll
        for (int ks = 0; ks < 4; ks++) {
            #pragma unroll
            for (int nb = 0; nb < 4; nb++) {
                uint32_t kh4[4], kl4[4];
                uint32_t off = (uint32_t)((nb * 16 + kn_row) * F_LD
                                          + ks * 16 + kn_col) * 2u;
                ldsm_x4(kh4, uKh + off);
                ldsm_x4(kl4, uKl + off);
                mma_bf16(s[2 * nb],     qfh[ks], kh4[0], kh4[1]);
                mma_bf16(s[2 * nb],     qfh[ks], kl4[0], kl4[1]);
                mma_bf16(s[2 * nb],     qfl[ks], kh4[0], kh4[1]);
                mma_bf16(s[2 * nb + 1], qfh[ks], kh4[2], kh4[3]);
                mma_bf16(s[2 * nb + 1], qfh[ks], kl4[2], kl4[3]);
                mma_bf16(s[2 * nb + 1], qfl[ks], kh4[2], kh4[3]);
            }
        }

        // ---- online softmax ----
        float mx0 = -1e30f, mx1 = -1e30f;
        #pragma unroll
        for (int i = 0; i < 8; i++) {
            #pragma unroll
            for (int t = 0; t < 4; t++) s[i][t] *= scale;
            mx0 = fmaxf(mx0, fmaxf(s[i][0], s[i][1]));
            mx1 = fmaxf(mx1, fmaxf(s[i][2], s[i][3]));
        }
        #pragma unroll
        for (int off = 1; off < 4; off <<= 1) {
            mx0 = fmaxf(mx0, __shfl_xor_sync(0xffffffffu, mx0, off));
            mx1 = fmaxf(mx1, __shfl_xor_sync(0xffffffffu, mx1, off));
        }
        const float mn0 = fmaxf(m0, mx0), mn1 = fmaxf(m1, mx1);
        const float f0 = __expf(m0 - mn0), f1 = __expf(m1 - mn1);
        float ls0 = 0.f, ls1 = 0.f;
        #pragma unroll
        for (int i = 0; i < 8; i++) {
            s[i][0] = __expf(s[i][0] - mn0);
            s[i][1] = __expf(s[i][1] - mn0);
            s[i][2] = __expf(s[i][2] - mn1);
            s[i][3] = __expf(s[i][3] - mn1);
            ls0 += s[i][0] + s[i][1];
            ls1 += s[i][2] + s[i][3];
        }
        #pragma unroll
        for (int off = 1; off < 4; off <<= 1) {
            ls0 += __shfl_xor_sync(0xffffffffu, ls0, off);
            ls1 += __shfl_xor_sync(0xffffffffu, ls1, off);
        }
        l0 = l0 * f0 + ls0;  m0 = mn0;
        l1 = l1 * f1 + ls1;  m1 = mn1;
        #pragma unroll
        for (int i = 0; i < 8; i++) {
            o[i][0] *= f0; o[i][1] *= f0;
            o[i][2] *= f1; o[i][3] *= f1;
        }

        // ---- O += P V ----
        #pragma unroll
        for (int t = 0; t < 4; t++) {
            uint32_t ah[4], al[4];
            #pragma unroll
            for (int half = 0; half < 2; half++) {
                const float* sj = s[2 * t + half];
                float h0f = __bfloat162float(__float2bfloat16(sj[0]));
                float h1f = __bfloat162float(__float2bfloat16(sj[1]));
                float h2f = __bfloat162float(__float2bfloat16(sj[2]));
                float h3f = __bfloat162float(__float2bfloat16(sj[3]));
                ah[2 * half]     = pack_bf16x2(h0f, h1f);
                ah[2 * half + 1] = pack_bf16x2(h2f, h3f);
                al[2 * half]     = pack_bf16x2(sj[0] - h0f, sj[1] - h1f);
                al[2 * half + 1] = pack_bf16x2(sj[2] - h2f, sj[3] - h3f);
            }
            #pragma unroll
            for (int nb = 0; nb < 4; nb++) {
                uint32_t vh4[4], vl4[4];
                uint32_t off = (uint32_t)((t * 16 + v_row) * F_LD
                                          + nb * 16 + v_col) * 2u;
                ldsm_x4_t(vh4, uVh + off);
                ldsm_x4_t(vl4, uVl + off);
                mma_bf16(o[2 * nb],     ah, vh4[0], vh4[1]);
                mma_bf16(o[2 * nb],     ah, vl4[0], vl4[1]);
                mma_bf16(o[2 * nb],     al, vh4[0], vh4[1]);
                mma_bf16(o[2 * nb + 1], ah, vh4[2], vh4[3]);
                mma_bf16(o[2 * nb + 1], ah, vl4[2], vl4[3]);
                mma_bf16(o[2 * nb + 1], al, vh4[2], vh4[3]);
            }
        }
        __syncthreads();
    }

    // ---- epilogue ----
    const float il0 = 1.f / l0, il1 = 1.f / l1;
    const int sq0 = qt * 128 + w * 16 + gid;
    #pragma unroll
    for (int ni = 0; ni < 8; ni++) {
        const int col = h * HD + ni * 8 + tig * 2;
        {
            float v0 = o[ni][0] * il0, v1 = o[ni][1] * il0;
            uint32_t hp, lp;
            split2(v0, v1, hp, lp);
            const size_t a = ((size_t)(b * SEQL + sq0)) * DIM + col;
            *(uint32_t*)(&Oh[a]) = hp;
            *(uint32_t*)(&Ol[a]) = lp;
        }
        {
            float v0 = o[ni][2] * il1, v1 = o[ni][3] * il1;
            uint32_t hp, lp;
            split2(v0, v1, hp, lp);
            const size_t a = ((size_t)(b * SEQL + sq0 + 8)) * DIM + col;
            *(uint32_t*)(&Oh[a]) = hp;
            *(uint32_t*)(&Ol[a]) = lp;
        }
    }
}

// ---------------------------------------------------------------------------
// Launch
// ---------------------------------------------------------------------------
extern "C" void kernel_launch(void* const* d_in, const int* in_sizes, int n_in,
                              void* d_out, int out_size)
{
    const float* x    = (const float*)d_in[0];
    const float* Wqkv = (const float*)d_in[1];
    const float* bqkv = (const float*)d_in[2];
    const float* Wout = (const float*)d_in[3];
    const float* bout = (const float*)d_in[4];
    float* out = (float*)d_out;

    void* p;
    cudaGetSymbolAddress(&p, g_x_hi);    __nv_bfloat16* xh = (__nv_bfloat16*)p;
    cudaGetSymbolAddress(&p, g_x_lo);    __nv_bfloat16* xl = (__nv_bfloat16*)p;
    cudaGetSymbolAddress(&p, g_wqkv_hi); __nv_bfloat16* wqh = (__nv_bfloat16*)p;
    cudaGetSymbolAddress(&p, g_wqkv_lo); __nv_bfloat16* wql = (__nv_bfloat16*)p;
    cudaGetSymbolAddress(&p, g_wout_hi); __nv_bfloat16* woh = (__nv_bfloat16*)p;
    cudaGetSymbolAddress(&p, g_wout_lo); __nv_bfloat16* wol = (__nv_bfloat16*)p;
    cudaGetSymbolAddress(&p, g_q_hi);    __nv_bfloat16* qh = (__nv_bfloat16*)p;
    cudaGetSymbolAddress(&p, g_q_lo);    __nv_bfloat16* ql = (__nv_bfloat16*)p;
    cudaGetSymbolAddress(&p, g_k_hi);    __nv_bfloat16* kh = (__nv_bfloat16*)p;
    cudaGetSymbolAddress(&p, g_k_lo);    __nv_bfloat16* kl = (__nv_bfloat16*)p;
    cudaGetSymbolAddress(&p, g_v_hi);    __nv_bfloat16* vh = (__nv_bfloat16*)p;
    cudaGetSymbolAddress(&p, g_v_lo);    __nv_bfloat16* vl = (__nv_bfloat16*)p;
    cudaGetSymbolAddress(&p, g_at_hi);   __nv_bfloat16* ah = (__nv_bfloat16*)p;
    cudaGetSymbolAddress(&p, g_at_lo);   __nv_bfloat16* al = (__nv_bfloat16*)p;
    cudaGetSymbolAddress(&p, g_cos);     float* ctab = (float*)p;
    cudaGetSymbolAddress(&p, g_sin);     float* stab = (float*)p;

    cudaFuncSetAttribute(gemm_qkv_rope, cudaFuncAttributeMaxDynamicSharedMemorySize,
                         G_SMEM_BYTES);
    cudaFuncSetAttribute(mma_gemm, cudaFuncAttributeMaxDynamicSharedMemorySize,
                         G_SMEM_BYTES);
    cudaFuncSetAttribute(flash_mma, cudaFuncAttributeMaxDynamicSharedMemorySize,
                         F_SMEM_BYTES);

    // 0) prep
    split_kernel<<<(MROWS * DIM) / 256, 256>>>(x, xh, xl, MROWS * DIM);
    split_kernel<<<(DIM * D3) / 256, 256>>>(Wqkv, wqh, wql, DIM * D3);
    split_kernel<<<(DIM * DIM) / 256, 256>>>(Wout, woh, wol, DIM * DIM);
    rope_table_kernel<<<(SEQL * 32) / 256, 256>>>(ctab, stab);

    // 1) QKV projection + bias + RoPE + split (fused)
    gemm_qkv_rope<<<dim3(D3 / 128, MROWS / 128), 256, G_SMEM_BYTES>>>(
        xh, xl, wqh, wql, bqkv, ctab, stab, qh, ql, kh, kl, vh, vl);

    // 2) flash attention (128-row q tiles)
    flash_mma<<<dim3(SEQL / 128, BATCH * NHEAD), 256, F_SMEM_BYTES>>>(
        qh, ql, kh, kl, vh, vl, ah, al);

    // 3) output projection
    mma_gemm<<<dim3(DIM / 128, MROWS / 128), 256, G_SMEM_BYTES>>>(
        ah, al, woh, wol, bout, out, MROWS, DIM, DIM);
}